// round 2
// baseline (speedup 1.0000x reference)
#include <cuda_runtime.h>

// ---------------------------------------------------------------------------
// Problem constants
//   B=8, C_IN=256, DIM=64, HEADS=8, D_IN=128, DKQ=8, DV=16, QKV=32
//   NB = B*DIM = 512 rows per axial pass, NTOK = NB*64 = 32768
// ---------------------------------------------------------------------------
#define EPSV 1e-5f

// ------------------------- scratch (global, static) ------------------------
__device__ float g_conv1[128 * 32768];        // conv_in output [o][n], n=(b,hw)
__device__ float g_x1  [128 * 32768];         // bn+relu, transposed to [c][(b,w)*64+h]
__device__ float g_qkv [256 * 32768];         // qkv [o][(bb)*64+d]
__device__ float g_outb[2 * 512 * 128 * 64];  // att out [s][bb][c2][d]
__device__ float g_x2  [128 * 32768];         // combined att_h out -> [c][(b,h)*64+w]
__device__ float g_x3  [128 * 32768];         // combined att_w out -> [b][c][h][w]
__device__ float g_co  [256 * 32768];         // conv_out [o][n]
__device__ float g_part[512 * 24 * 2];        // attn-BN partial sums per (bb, ch)
__device__ float g_sum [512];                 // per-channel (sum, sumsq)
__device__ float g_sc  [256];
__device__ float g_sh  [256];
__device__ float g_scA [24];
__device__ float g_shA [24];

// ------------------------------ helpers ------------------------------------
__device__ __forceinline__ void blockReduce2(float& a, float& b) {
    __shared__ float sa[8], sb[8];
    int lane = threadIdx.x & 31, w = threadIdx.x >> 5;
#pragma unroll
    for (int o = 16; o > 0; o >>= 1) {
        a += __shfl_xor_sync(0xffffffffu, a, o);
        b += __shfl_xor_sync(0xffffffffu, b, o);
    }
    if (lane == 0) { sa[w] = a; sb[w] = b; }
    __syncthreads();
    a = (threadIdx.x < 8) ? sa[threadIdx.x] : 0.f;
    b = (threadIdx.x < 8) ? sb[threadIdx.x] : 0.f;
    if (w == 0) {
#pragma unroll
        for (int o = 4; o > 0; o >>= 1) {
            a += __shfl_xor_sync(0xffffffffu, a, o);
            b += __shfl_xor_sync(0xffffffffu, b, o);
        }
    }
}

// ------------------------------ GEMM ----------------------------------------
// C[M][N] = A[M][K] * B[K][N].  A row-major.
// MODE 0: B[k*N + n] (row-major, N contiguous)
// MODE 1: B is a 4D tensor [b][k][4096]; column n=(b*4096+hw): B[((n>>12)*K+k)*4096 + (n&4095)]
// Block tile 128x128, BK=16, 256 threads, 8x8 per thread.
template <int MODE>
__global__ void __launch_bounds__(256) gemm_k(const float* __restrict__ A,
                                              const float* __restrict__ Bm,
                                              float* __restrict__ C,
                                              int M, int N, int K) {
    __shared__ float As[16][128];
    __shared__ float Bs[16][128];
    int tid = threadIdx.x;
    int bm = blockIdx.y * 128;
    int bn = blockIdx.x * 128;
    int tx = tid & 15, ty = tid >> 4;

    float acc[8][8];
#pragma unroll
    for (int i = 0; i < 8; i++)
#pragma unroll
        for (int j = 0; j < 8; j++) acc[i][j] = 0.f;

    for (int k0 = 0; k0 < K; k0 += 16) {
#pragma unroll
        for (int l = 0; l < 2; l++) {
            int fa = tid * 2 + l;
            int row = fa >> 2, c4 = (fa & 3) << 2;
            float4 v = *(const float4*)(A + (bm + row) * K + k0 + c4);
            As[c4 + 0][row] = v.x; As[c4 + 1][row] = v.y;
            As[c4 + 2][row] = v.z; As[c4 + 3][row] = v.w;
        }
#pragma unroll
        for (int l = 0; l < 2; l++) {
            int fb = tid * 2 + l;
            int row = fb >> 5, c4 = (fb & 31) << 2;
            int n = bn + c4;
            const float* src;
            if (MODE == 0) src = Bm + (k0 + row) * N + n;
            else           src = Bm + ((n >> 12) * K + k0 + row) * 4096 + (n & 4095);
            *(float4*)&Bs[row][c4] = *(const float4*)src;
        }
        __syncthreads();
#pragma unroll
        for (int k = 0; k < 16; k++) {
            float4 a0 = *(const float4*)&As[k][ty * 8];
            float4 a1 = *(const float4*)&As[k][ty * 8 + 4];
            float4 b0 = *(const float4*)&Bs[k][tx * 8];
            float4 b1 = *(const float4*)&Bs[k][tx * 8 + 4];
            float av[8] = {a0.x, a0.y, a0.z, a0.w, a1.x, a1.y, a1.z, a1.w};
            float bv[8] = {b0.x, b0.y, b0.z, b0.w, b1.x, b1.y, b1.z, b1.w};
#pragma unroll
            for (int i = 0; i < 8; i++)
#pragma unroll
                for (int j = 0; j < 8; j++)
                    acc[i][j] = fmaf(av[i], bv[j], acc[i][j]);
        }
        __syncthreads();
    }
#pragma unroll
    for (int i = 0; i < 8; i++) {
        int row = bm + ty * 8 + i;
        float4* dst = (float4*)(C + (size_t)row * N + bn + tx * 8);
        dst[0] = make_float4(acc[i][0], acc[i][1], acc[i][2], acc[i][3]);
        dst[1] = make_float4(acc[i][4], acc[i][5], acc[i][6], acc[i][7]);
    }
}

// ---------------------- per-channel sum/sumsq (contiguous rows) -------------
__global__ void __launch_bounds__(256) reduce_rows_k(const float* __restrict__ src,
                                                     int rowlen, float* __restrict__ out) {
    int ch = blockIdx.x;
    const float* p = src + (size_t)ch * rowlen;
    float s = 0.f, ss = 0.f;
    for (int i = threadIdx.x * 4; i < rowlen; i += 1024) {
        float4 v = *(const float4*)(p + i);
        s += v.x + v.y + v.z + v.w;
        ss = fmaf(v.x, v.x, ss); ss = fmaf(v.y, v.y, ss);
        ss = fmaf(v.z, v.z, ss); ss = fmaf(v.w, v.w, ss);
    }
    blockReduce2(s, ss);
    if (threadIdx.x == 0) { out[ch * 2] = s; out[ch * 2 + 1] = ss; }
}

// ------------------- per-channel stats over g_outb ([s][bb][c2][d]) ---------
__global__ void __launch_bounds__(256) reduce_outb_k(const float* __restrict__ outb,
                                                     float* __restrict__ out) {
    int ch = blockIdx.x;               // ch = s*128 + c2
    int s_ = ch >> 7, c2 = ch & 127;
    const float* base = outb + ((size_t)s_ * 512 * 128 + c2) * 64;
    float s = 0.f, ss = 0.f;
    for (int t = threadIdx.x; t < 512 * 64; t += 256) {
        int bb = t >> 6, d = t & 63;
        float v = base[bb * 8192 + d];
        s += v; ss = fmaf(v, v, ss);
    }
    blockReduce2(s, ss);
    if (threadIdx.x == 0) { out[ch * 2] = s; out[ch * 2 + 1] = ss; }
}

// --------------------------- BN finalize ------------------------------------
__global__ void finalize_k(const float* __restrict__ sums, const float* __restrict__ gamma,
                           const float* __restrict__ beta, int nchan, float invN,
                           float* __restrict__ sc, float* __restrict__ sh) {
    int c = blockIdx.x * blockDim.x + threadIdx.x;
    if (c < nchan) {
        float mean = sums[c * 2] * invN;
        float var  = sums[c * 2 + 1] * invN - mean * mean;
        float s = gamma[c] * rsqrtf(var + EPSV);
        sc[c] = s;
        sh[c] = beta[c] - mean * s;
    }
}

// ----- T1: bn+relu + transpose conv1[o][b][h][w] -> x1[o][(b*64+w)*64 + h] ---
__global__ void __launch_bounds__(256) t1_k(const float* __restrict__ conv1,
                                            const float* __restrict__ sc,
                                            const float* __restrict__ sh,
                                            float* __restrict__ x1) {
    __shared__ float tile[64][65];
    int o = blockIdx.x, b = blockIdx.y;
    float s = sc[o], t = sh[o];
    const float* src = conv1 + (size_t)o * 32768 + b * 4096;
    float* dst = x1 + (size_t)o * 32768 + b * 4096;
    for (int e = threadIdx.x; e < 4096; e += 256) {
        int h = e >> 6, w = e & 63;
        tile[w][h] = fmaxf(fmaf(src[e], s, t), 0.f);
    }
    __syncthreads();
    for (int e = threadIdx.x; e < 4096; e += 256) {
        int w = e >> 6, h = e & 63;
        dst[e] = tile[w][h];   // dst index = (b*64+w)*64 + h
    }
}

// ----- attention-logit BN statistics: recompute qr/kr/dots, partial sums ----
__global__ void __launch_bounds__(256) attA_stats_k(const float* __restrict__ qkv,
                                                    const float* __restrict__ rel,
                                                    float* __restrict__ part) {
    int bb = blockIdx.x >> 3, h = blockIdx.x & 7;
    __shared__ float qs[8][64], ks[8][64];
    __shared__ float rq[8][127], rk[8][127];
    __shared__ float wsum[8][6];
    int tid = threadIdx.x;
    for (int e = tid; e < 1024; e += 256) {
        int r = e >> 6, d = e & 63;
        float v = qkv[(r * 8 + h) * 32768 + bb * 64 + d];
        if (r < 8) qs[r][d] = v; else ks[r - 8][d] = v;
    }
    for (int e = tid; e < 16 * 127; e += 256) {
        int r = e / 127, p2 = e % 127;
        float v = rel[e];
        if (r < 8) rq[r][p2] = v; else rk[r - 8][p2] = v;
    }
    __syncthreads();
    int d = tid >> 2, j0 = (tid & 3) << 4;
    float qv[8], kv[8];
#pragma unroll
    for (int i = 0; i < 8; i++) { qv[i] = qs[i][d]; kv[i] = ks[i][d]; }
    float sv[3] = {0, 0, 0}, ssv[3] = {0, 0, 0};
    for (int j = j0; j < j0 + 16; j++) {
        int p = d - j + 63;
        float a = 0.f, b2 = 0.f, c = 0.f;
#pragma unroll
        for (int i = 0; i < 8; i++) {
            a  = fmaf(qv[i], rq[i][p], a);
            b2 = fmaf(kv[i], rk[i][p], b2);
            c  = fmaf(qv[i], ks[i][j], c);
        }
        sv[0] += a;  ssv[0] = fmaf(a, a, ssv[0]);
        sv[1] += b2; ssv[1] = fmaf(b2, b2, ssv[1]);
        sv[2] += c;  ssv[2] = fmaf(c, c, ssv[2]);
    }
    int lane = tid & 31, w = tid >> 5;
#pragma unroll
    for (int t = 0; t < 3; t++)
#pragma unroll
        for (int o = 16; o > 0; o >>= 1) {
            sv[t]  += __shfl_xor_sync(0xffffffffu, sv[t], o);
            ssv[t] += __shfl_xor_sync(0xffffffffu, ssv[t], o);
        }
    if (lane == 0) {
#pragma unroll
        for (int t = 0; t < 3; t++) { wsum[w][t * 2] = sv[t]; wsum[w][t * 2 + 1] = ssv[t]; }
    }
    __syncthreads();
    if (tid < 6) {
        float acc = 0.f;
#pragma unroll
        for (int w2 = 0; w2 < 8; w2++) acc += wsum[w2][tid];
        part[(bb * 24 + h * 3) * 2 + tid] = acc;   // (t*2 + c) packed in tid
    }
}

__global__ void __launch_bounds__(256) attA_fin_k(const float* __restrict__ part,
                                                  const float* __restrict__ ga,
                                                  const float* __restrict__ ba,
                                                  float* __restrict__ scA,
                                                  float* __restrict__ shA) {
    int ch = blockIdx.x;   // h*3 + t, 24 channels
    float s = 0.f, ss = 0.f;
    for (int bb = threadIdx.x; bb < 512; bb += 256) {
        s  += part[(bb * 24 + ch) * 2];
        ss += part[(bb * 24 + ch) * 2 + 1];
    }
    blockReduce2(s, ss);
    if (threadIdx.x == 0) {
        const float invN = 1.0f / 2097152.0f;   // 512*64*64
        float mean = s * invN;
        float var  = ss * invN - mean * mean;
        float sc = ga[ch] * rsqrtf(var + EPSV);
        scA[ch] = sc;
        shA[ch] = ba[ch] - mean * sc;
    }
}

// ----- attention mainloop: logits (BN'd) -> softmax -> sv & sve -------------
__global__ void __launch_bounds__(256) att_main_k(const float* __restrict__ qkv,
                                                  const float* __restrict__ rel,
                                                  const float* __restrict__ scA,
                                                  const float* __restrict__ shA,
                                                  float* __restrict__ outb) {
    int bb = blockIdx.x >> 3, h = blockIdx.x & 7;
    __shared__ float qs[8][64], ks[8][64], vs[16][64];
    __shared__ float rq[8][127], rk[8][127], rv[16][127];
    __shared__ float attn[64][65];
    int tid = threadIdx.x;
    for (int e = tid; e < 2048; e += 256) {
        int r = e >> 6, d = e & 63;
        float v = qkv[(r * 8 + h) * 32768 + bb * 64 + d];
        if (r < 8) qs[r][d] = v;
        else if (r < 16) ks[r - 8][d] = v;
        else vs[r - 16][d] = v;
    }
    for (int e = tid; e < 32 * 127; e += 256) {
        int r = e / 127, p2 = e % 127;
        float v = rel[e];
        if (r < 8) rq[r][p2] = v;
        else if (r < 16) rk[r - 8][p2] = v;
        else rv[r - 16][p2] = v;
    }
    float sc0 = scA[h * 3 + 0], sh0 = shA[h * 3 + 0];
    float sc1 = scA[h * 3 + 1], sh1 = shA[h * 3 + 1];
    float sc2 = scA[h * 3 + 2], sh2 = shA[h * 3 + 2];
    __syncthreads();
    {
        int d = tid >> 2, j0 = (tid & 3) << 4;
        float qv[8], kv[8];
#pragma unroll
        for (int i = 0; i < 8; i++) { qv[i] = qs[i][d]; kv[i] = ks[i][d]; }
        for (int j = j0; j < j0 + 16; j++) {
            int p = d - j + 63;
            float a = 0.f, bq = 0.f, c = 0.f;
#pragma unroll
            for (int i = 0; i < 8; i++) {
                a  = fmaf(qv[i], rq[i][p], a);
                bq = fmaf(kv[i], rk[i][p], bq);
                c  = fmaf(qv[i], ks[i][j], c);
            }
            attn[d][j] = fmaf(a, sc0, sh0) + fmaf(bq, sc1, sh1) + fmaf(c, sc2, sh2);
        }
    }
    __syncthreads();
    {   // softmax: 8 warps x 8 rows
        int w = tid >> 5, lane = tid & 31;
        for (int r = 0; r < 8; r++) {
            int d = w * 8 + r;
            float v0 = attn[d][lane], v1 = attn[d][lane + 32];
            float mx = fmaxf(v0, v1);
#pragma unroll
            for (int o = 16; o > 0; o >>= 1) mx = fmaxf(mx, __shfl_xor_sync(0xffffffffu, mx, o));
            float e0 = __expf(v0 - mx), e1 = __expf(v1 - mx);
            float sm = e0 + e1;
#pragma unroll
            for (int o = 16; o > 0; o >>= 1) sm += __shfl_xor_sync(0xffffffffu, sm, o);
            float inv = 1.f / sm;
            attn[d][lane] = e0 * inv;
            attn[d][lane + 32] = e1 * inv;
        }
    }
    __syncthreads();
    {   // sv[i][d] = sum_j attn[d][j] v[i][j]; sve[i][d] = sum_j attn[d][j] rv[i][d-j+63]
        int d = tid & 63;
        int ig = tid >> 6;            // 0..3 -> i = ig*4 + ii
        float asv[4] = {0, 0, 0, 0}, asve[4] = {0, 0, 0, 0};
        for (int j = 0; j < 64; j++) {
            float a = attn[d][j];
            int p = d - j + 63;
#pragma unroll
            for (int ii = 0; ii < 4; ii++) {
                int i = ig * 4 + ii;
                asv[ii]  = fmaf(a, vs[i][j], asv[ii]);
                asve[ii] = fmaf(a, rv[i][p], asve[ii]);
            }
        }
        size_t base_sve = ((size_t)bb * 128 + h * 16) * 64 + d;          // s=0
        size_t base_sv  = ((size_t)(512 + bb) * 128 + h * 16) * 64 + d;  // s=1
#pragma unroll
        for (int ii = 0; ii < 4; ii++) {
            int i = ig * 4 + ii;
            outb[base_sve + (size_t)i * 64] = asve[ii];
            outb[base_sv  + (size_t)i * 64] = asv[ii];
        }
    }
}

// ----- T2: BN + sum over s + transpose (b,w,c2,h) -> x2[c2][(b*64+h)*64+w] ---
__global__ void __launch_bounds__(256) t2_k(const float* __restrict__ outb,
                                            const float* __restrict__ sc,
                                            const float* __restrict__ sh,
                                            float* __restrict__ x2) {
    __shared__ float tile[64][65];
    int c2 = blockIdx.x, b = blockIdx.y;
    float s0 = sc[c2],       h0 = sh[c2];
    float s1 = sc[128 + c2], h1 = sh[128 + c2];
    const float* base0 = outb + ((size_t)(b * 64) * 128 + c2) * 64;
    const float* base1 = base0 + (size_t)512 * 128 * 64;
    for (int e = threadIdx.x; e < 4096; e += 256) {
        int w = e >> 6, h = e & 63;
        float v = fmaf(base0[w * 8192 + h], s0, h0) + fmaf(base1[w * 8192 + h], s1, h1);
        tile[h][w] = v;
    }
    __syncthreads();
    float* dst = x2 + (size_t)c2 * 32768 + b * 4096;
    for (int e = threadIdx.x; e < 4096; e += 256) {
        int h = e >> 6, w = e & 63;
        dst[e] = tile[h][w];   // index = (b*64+h)*64 + w
    }
}

// ----- T3: BN + sum over s + relu -> x3[b][c2][h][w] (no transpose needed) --
__global__ void __launch_bounds__(256) t3_k(const float* __restrict__ outb,
                                            const float* __restrict__ sc,
                                            const float* __restrict__ sh,
                                            float* __restrict__ x3) {
    int g = blockIdx.x * 256 + threadIdx.x;  // over 4,194,304
    int w  = g & 63;
    int r  = g >> 6;
    int h  = r & 63;
    int c2 = (r >> 6) & 127;
    int b  = r >> 13;
    int bb = b * 64 + h;
    float v = fmaf(outb[(bb * 128 + c2) * 64 + w], sc[c2], sh[c2])
            + fmaf(outb[((512 + bb) * 128 + c2) * 64 + w], sc[128 + c2], sh[128 + c2]);
    x3[g] = fmaxf(v, 0.f);
}

// ----- final: y = relu(bn(conv_out) + x_in) ---------------------------------
__global__ void __launch_bounds__(256) final_k(const float* __restrict__ co,
                                               const float* __restrict__ sc,
                                               const float* __restrict__ sh,
                                               const float* __restrict__ x_in,
                                               float* __restrict__ out) {
    int g = blockIdx.x * 256 + threadIdx.x;  // over 8,388,608
    int o  = (g >> 12) & 255;
    int b  = g >> 20;
    int hw = g & 4095;
    float v = fmaf(co[o * 32768 + b * 4096 + hw], sc[o], sh[o]) + x_in[g];
    out[g] = fmaxf(v, 0.f);
}

// ---------------------------------------------------------------------------
extern "C" void kernel_launch(void* const* d_in, const int* in_sizes, int n_in,
                              void* d_out, int out_size) {
    const float* x_in   = (const float*)d_in[0];
    const float* w_in   = (const float*)d_in[1];
    const float* g_in   = (const float*)d_in[2];
    const float* b_in   = (const float*)d_in[3];
    const float* w_out  = (const float*)d_in[4];
    const float* gout   = (const float*)d_in[5];
    const float* bout   = (const float*)d_in[6];
    const float* wqkv_h = (const float*)d_in[7];
    const float* rel_h  = (const float*)d_in[8];
    const float* ga_h   = (const float*)d_in[9];
    const float* ba_h   = (const float*)d_in[10];
    const float* go_h   = (const float*)d_in[11];
    const float* bo_h   = (const float*)d_in[12];
    const float* wqkv_w = (const float*)d_in[13];
    const float* rel_w  = (const float*)d_in[14];
    const float* ga_w   = (const float*)d_in[15];
    const float* ba_w   = (const float*)d_in[16];
    const float* go_w   = (const float*)d_in[17];
    const float* bo_w   = (const float*)d_in[18];
    float* out = (float*)d_out;

    float *conv1, *x1, *qkv, *outb, *x2, *x3, *co, *part, *sum, *sc, *sh, *scA, *shA;
    cudaGetSymbolAddress((void**)&conv1, g_conv1);
    cudaGetSymbolAddress((void**)&x1,    g_x1);
    cudaGetSymbolAddress((void**)&qkv,   g_qkv);
    cudaGetSymbolAddress((void**)&outb,  g_outb);
    cudaGetSymbolAddress((void**)&x2,    g_x2);
    cudaGetSymbolAddress((void**)&x3,    g_x3);
    cudaGetSymbolAddress((void**)&co,    g_co);
    cudaGetSymbolAddress((void**)&part,  g_part);
    cudaGetSymbolAddress((void**)&sum,   g_sum);
    cudaGetSymbolAddress((void**)&sc,    g_sc);
    cudaGetSymbolAddress((void**)&sh,    g_sh);
    cudaGetSymbolAddress((void**)&scA,   g_scA);
    cudaGetSymbolAddress((void**)&shA,   g_shA);

    const float invTok = 1.0f / 32768.0f;

    // 1) conv_in: conv1[128][32768] = w_in @ x_in
    gemm_k<1><<<dim3(256, 1), 256>>>(w_in, x_in, conv1, 128, 32768, 256);
    // 2) BN-in stats + finalize
    reduce_rows_k<<<128, 256>>>(conv1, 32768, sum);
    finalize_k<<<1, 256>>>(sum, g_in, b_in, 128, invTok, sc, sh);
    // 3) bn+relu + transpose -> x1
    t1_k<<<dim3(128, 8), 256>>>(conv1, sc, sh, x1);

    // ---------------- axial attention along H ----------------
    gemm_k<0><<<dim3(256, 2), 256>>>(wqkv_h, x1, qkv, 256, 32768, 128);
    attA_stats_k<<<4096, 256>>>(qkv, rel_h, part);
    attA_fin_k<<<24, 256>>>(part, ga_h, ba_h, scA, shA);
    att_main_k<<<4096, 256>>>(qkv, rel_h, scA, shA, outb);
    reduce_outb_k<<<256, 256>>>(outb, sum);
    finalize_k<<<1, 256>>>(sum, go_h, bo_h, 256, invTok, sc, sh);
    t2_k<<<dim3(128, 8), 256>>>(outb, sc, sh, x2);

    // ---------------- axial attention along W ----------------
    gemm_k<0><<<dim3(256, 2), 256>>>(wqkv_w, x2, qkv, 256, 32768, 128);
    attA_stats_k<<<4096, 256>>>(qkv, rel_w, part);
    attA_fin_k<<<24, 256>>>(part, ga_w, ba_w, scA, shA);
    att_main_k<<<4096, 256>>>(qkv, rel_w, scA, shA, outb);
    reduce_outb_k<<<256, 256>>>(outb, sum);
    finalize_k<<<1, 256>>>(sum, go_w, bo_w, 256, invTok, sc, sh);
    t3_k<<<16384, 256>>>(outb, sc, sh, x3);

    // ---------------- conv_out + BN + residual + relu ----------------
    gemm_k<1><<<dim3(256, 2), 256>>>(w_out, x3, co, 256, 32768, 128);
    reduce_rows_k<<<256, 256>>>(co, 32768, sum);
    finalize_k<<<1, 256>>>(sum, gout, bout, 256, invTok, sc, sh);
    final_k<<<32768, 256>>>(co, sc, sh, x_in, out);
}

// round 3
// speedup vs baseline: 1.1387x; 1.1387x over previous
#include <cuda_runtime.h>

// ---------------------------------------------------------------------------
// Problem constants
//   B=8, C_IN=256, DIM=64, HEADS=8, D_IN=128, DKQ=8, DV=16, QKV=32
// ---------------------------------------------------------------------------
#define EPSV 1e-5f

// ------------------------- scratch (global, static) ------------------------
__device__ float g_conv1[128 * 32768];
__device__ float g_x1  [128 * 32768];
__device__ float g_qkv [256 * 32768];
__device__ float g_outb[2 * 512 * 128 * 64];
__device__ float g_x2  [128 * 32768];
__device__ float g_x3  [128 * 32768];
__device__ float g_co  [256 * 32768];
__device__ float g_part[512 * 24 * 2];
__device__ float g_sum [512];
__device__ float g_sc  [256];
__device__ float g_sh  [256];
__device__ float g_scA [24];
__device__ float g_shA [24];
__device__ float g_Wt  [72 * 64];   // windowed correlation tables (q:36, k:36)
__device__ float g_St  [16 * 64];   // windowed sums (q:8, k:8)

// ------------------------------ helpers ------------------------------------
__device__ __forceinline__ float warpSum(float v) {
#pragma unroll
    for (int o = 16; o > 0; o >>= 1) v += __shfl_xor_sync(0xffffffffu, v, o);
    return v;
}

__device__ __forceinline__ void blockReduce2(float& a, float& b) {
    __shared__ float sa[8], sb[8];
    int lane = threadIdx.x & 31, w = threadIdx.x >> 5;
#pragma unroll
    for (int o = 16; o > 0; o >>= 1) {
        a += __shfl_xor_sync(0xffffffffu, a, o);
        b += __shfl_xor_sync(0xffffffffu, b, o);
    }
    if (lane == 0) { sa[w] = a; sb[w] = b; }
    __syncthreads();
    a = (threadIdx.x < 8) ? sa[threadIdx.x] : 0.f;
    b = (threadIdx.x < 8) ? sb[threadIdx.x] : 0.f;
    if (w == 0) {
#pragma unroll
        for (int o = 4; o > 0; o >>= 1) {
            a += __shfl_xor_sync(0xffffffffu, a, o);
            b += __shfl_xor_sync(0xffffffffu, b, o);
        }
    }
}

// ------------------------------ GEMM (double-buffered) ----------------------
// C[M][N] = A[M][K] * B[K][N]. MODE 0: B row-major. MODE 1: B is [b][k][4096].
template <int MODE>
__global__ void __launch_bounds__(256) gemm_k(const float* __restrict__ A,
                                              const float* __restrict__ Bm,
                                              float* __restrict__ C,
                                              int M, int N, int K) {
    __shared__ float As[2][16][128];
    __shared__ float Bs[2][16][128];
    int tid = threadIdx.x;
    int bm = blockIdx.y * 128;
    int bn = blockIdx.x * 128;
    int tx = tid & 15, ty = tid >> 4;

    int faRow0 = (tid * 2) >> 2,     faC0 = ((tid * 2) & 3) << 2;
    int faRow1 = (tid * 2 + 1) >> 2, faC1 = ((tid * 2 + 1) & 3) << 2;
    int fbRow0 = (tid * 2) >> 5,     fbC0 = ((tid * 2) & 31) << 2;
    int fbRow1 = (tid * 2 + 1) >> 5, fbC1 = ((tid * 2 + 1) & 31) << 2;

    float acc[8][8];
#pragma unroll
    for (int i = 0; i < 8; i++)
#pragma unroll
        for (int j = 0; j < 8; j++) acc[i][j] = 0.f;

    // ---- load helpers ----
    auto ldA0 = [&](int k0) { return *(const float4*)(A + (bm + faRow0) * K + k0 + faC0); };
    auto ldA1 = [&](int k0) { return *(const float4*)(A + (bm + faRow1) * K + k0 + faC1); };
    auto ldB = [&](int k0, int row, int c4) {
        int n = bn + c4;
        const float* src = (MODE == 0)
            ? Bm + (size_t)(k0 + row) * N + n
            : Bm + ((size_t)(n >> 12) * K + k0 + row) * 4096 + (n & 4095);
        return *(const float4*)src;
    };

    // stage 0
    {
        float4 a0 = ldA0(0), a1 = ldA1(0);
        float4 b0 = ldB(0, fbRow0, fbC0), b1 = ldB(0, fbRow1, fbC1);
        As[0][faC0+0][faRow0]=a0.x; As[0][faC0+1][faRow0]=a0.y; As[0][faC0+2][faRow0]=a0.z; As[0][faC0+3][faRow0]=a0.w;
        As[0][faC1+0][faRow1]=a1.x; As[0][faC1+1][faRow1]=a1.y; As[0][faC1+2][faRow1]=a1.z; As[0][faC1+3][faRow1]=a1.w;
        *(float4*)&Bs[0][fbRow0][fbC0] = b0;
        *(float4*)&Bs[0][fbRow1][fbC1] = b1;
    }
    __syncthreads();

    int cur = 0;
    for (int k0 = 0; k0 < K; k0 += 16) {
        float4 pa0, pa1, pb0, pb1;
        bool nxt = (k0 + 16) < K;
        if (nxt) {
            pa0 = ldA0(k0 + 16); pa1 = ldA1(k0 + 16);
            pb0 = ldB(k0 + 16, fbRow0, fbC0); pb1 = ldB(k0 + 16, fbRow1, fbC1);
        }
#pragma unroll
        for (int k = 0; k < 16; k++) {
            float4 a0 = *(const float4*)&As[cur][k][ty * 8];
            float4 a1 = *(const float4*)&As[cur][k][ty * 8 + 4];
            float4 b0 = *(const float4*)&Bs[cur][k][tx * 8];
            float4 b1 = *(const float4*)&Bs[cur][k][tx * 8 + 4];
            float av[8] = {a0.x, a0.y, a0.z, a0.w, a1.x, a1.y, a1.z, a1.w};
            float bv[8] = {b0.x, b0.y, b0.z, b0.w, b1.x, b1.y, b1.z, b1.w};
#pragma unroll
            for (int i = 0; i < 8; i++)
#pragma unroll
                for (int j = 0; j < 8; j++)
                    acc[i][j] = fmaf(av[i], bv[j], acc[i][j]);
        }
        if (nxt) {
            int s = cur ^ 1;
            As[s][faC0+0][faRow0]=pa0.x; As[s][faC0+1][faRow0]=pa0.y; As[s][faC0+2][faRow0]=pa0.z; As[s][faC0+3][faRow0]=pa0.w;
            As[s][faC1+0][faRow1]=pa1.x; As[s][faC1+1][faRow1]=pa1.y; As[s][faC1+2][faRow1]=pa1.z; As[s][faC1+3][faRow1]=pa1.w;
            *(float4*)&Bs[s][fbRow0][fbC0] = pb0;
            *(float4*)&Bs[s][fbRow1][fbC1] = pb1;
            __syncthreads();
            cur = s;
        }
    }
#pragma unroll
    for (int i = 0; i < 8; i++) {
        int row = bm + ty * 8 + i;
        float4* dst = (float4*)(C + (size_t)row * N + bn + tx * 8);
        dst[0] = make_float4(acc[i][0], acc[i][1], acc[i][2], acc[i][3]);
        dst[1] = make_float4(acc[i][4], acc[i][5], acc[i][6], acc[i][7]);
    }
}

// ---------------------- per-channel sum/sumsq (contiguous rows) -------------
__global__ void __launch_bounds__(256) reduce_rows_k(const float* __restrict__ src,
                                                     int rowlen, float* __restrict__ out) {
    int ch = blockIdx.x;
    const float* p = src + (size_t)ch * rowlen;
    float s = 0.f, ss = 0.f;
    for (int i = threadIdx.x * 4; i < rowlen; i += 1024) {
        float4 v = *(const float4*)(p + i);
        s += v.x + v.y + v.z + v.w;
        ss = fmaf(v.x, v.x, ss); ss = fmaf(v.y, v.y, ss);
        ss = fmaf(v.z, v.z, ss); ss = fmaf(v.w, v.w, ss);
    }
    blockReduce2(s, ss);
    if (threadIdx.x == 0) { out[ch * 2] = s; out[ch * 2 + 1] = ss; }
}

// ------------------- per-channel stats over g_outb ([s][bb][c2][d]) ---------
__global__ void __launch_bounds__(256) reduce_outb_k(const float* __restrict__ outb,
                                                     float* __restrict__ out) {
    int ch = blockIdx.x;
    int s_ = ch >> 7, c2 = ch & 127;
    const float* base = outb + ((size_t)s_ * 512 * 128 + c2) * 64;
    float s = 0.f, ss = 0.f;
    for (int t = threadIdx.x; t < 512 * 64; t += 256) {
        int bb = t >> 6, d = t & 63;
        float v = base[bb * 8192 + d];
        s += v; ss = fmaf(v, v, ss);
    }
    blockReduce2(s, ss);
    if (threadIdx.x == 0) { out[ch * 2] = s; out[ch * 2 + 1] = ss; }
}

// --------------------------- BN finalize ------------------------------------
__global__ void finalize_k(const float* __restrict__ sums, const float* __restrict__ gamma,
                           const float* __restrict__ beta, int nchan, float invN,
                           float* __restrict__ sc, float* __restrict__ sh) {
    int c = blockIdx.x * blockDim.x + threadIdx.x;
    if (c < nchan) {
        float mean = sums[c * 2] * invN;
        float var  = sums[c * 2 + 1] * invN - mean * mean;
        float s = gamma[c] * rsqrtf(var + EPSV);
        sc[c] = s;
        sh[c] = beta[c] - mean * s;
    }
}

// ----- T1: bn+relu + transpose conv1[o][b][h][w] -> x1[o][(b*64+w)*64 + h] ---
__global__ void __launch_bounds__(256) t1_k(const float* __restrict__ conv1,
                                            const float* __restrict__ sc,
                                            const float* __restrict__ sh,
                                            float* __restrict__ x1) {
    __shared__ float tile[64][65];
    int o = blockIdx.x, b = blockIdx.y;
    float s = sc[o], t = sh[o];
    const float* src = conv1 + (size_t)o * 32768 + b * 4096;
    float* dst = x1 + (size_t)o * 32768 + b * 4096;
    for (int e = threadIdx.x; e < 4096; e += 256) {
        int h = e >> 6, w = e & 63;
        tile[w][h] = fmaxf(fmaf(src[e], s, t), 0.f);
    }
    __syncthreads();
    for (int e = threadIdx.x; e < 4096; e += 256) {
        int w = e >> 6, h = e & 63;
        dst[e] = tile[w][h];
    }
}

// ----- rel prep: windowed correlation + window-sum tables --------------------
__global__ void rel_prep_k(const float* __restrict__ rel,
                           float* __restrict__ W, float* __restrict__ S) {
    int t = threadIdx.x;
    if (t < 72) {
        int grp = (t < 36) ? 0 : 1;
        int pr  = (t < 36) ? t : t - 36;
        int i = 0, r = pr;
        while (r >= 8 - i) { r -= 8 - i; i++; }
        int i2 = i + r;
        const float* ra = rel + (grp * 8 + i)  * 127;
        const float* rb = rel + (grp * 8 + i2) * 127;
        float w = 0.f;
        for (int p = 0; p < 64; p++) w = fmaf(ra[p], rb[p], w);
        W[t * 64 + 0] = w;
        for (int d = 1; d < 64; d++) {
            w += ra[d + 63] * rb[d + 63] - ra[d - 1] * rb[d - 1];
            W[t * 64 + d] = w;
        }
    } else if (t < 88) {
        int rr = t - 72;
        const float* ra = rel + rr * 127;
        float s = 0.f;
        for (int p = 0; p < 64; p++) s += ra[p];
        S[rr * 64 + 0] = s;
        for (int d = 1; d < 64; d++) { s += ra[d + 63] - ra[d - 1]; S[rr * 64 + d] = s; }
    }
}

// ----- closed-form attention BN stats ----------------------------------------
__global__ void __launch_bounds__(256) att_stats_k(const float* __restrict__ qkv,
                                                   const float* __restrict__ Wt,
                                                   const float* __restrict__ St,
                                                   float* __restrict__ part) {
    __shared__ float Ws[72 * 64];
    __shared__ float Ss[16 * 64];
    int bb = blockIdx.x;
    int tid = threadIdx.x;
    for (int e = tid; e < 72 * 64; e += 256) Ws[e] = Wt[e];
    for (int e = tid; e < 16 * 64; e += 256) Ss[e] = St[e];
    __syncthreads();
    int h = tid >> 5, lane = tid & 31;
    float q[8][2], k[8][2];
#pragma unroll
    for (int i = 0; i < 8; i++) {
        const float* pq = qkv + (size_t)(i * 8 + h) * 32768 + bb * 64;
        const float* pk = qkv + (size_t)((8 + i) * 8 + h) * 32768 + bb * 64;
        q[i][0] = pq[lane]; q[i][1] = pq[lane + 32];
        k[i][0] = pk[lane]; k[i][1] = pk[lane + 32];
    }
    float s_qr = 0.f, s_kr = 0.f;
    float Qs[8], Ks[8];
#pragma unroll
    for (int i = 0; i < 8; i++) {
        s_qr = fmaf(q[i][0], Ss[i * 64 + lane], s_qr);
        s_qr = fmaf(q[i][1], Ss[i * 64 + lane + 32], s_qr);
        s_kr = fmaf(k[i][0], Ss[(8 + i) * 64 + lane], s_kr);
        s_kr = fmaf(k[i][1], Ss[(8 + i) * 64 + lane + 32], s_kr);
        Qs[i] = warpSum(q[i][0] + q[i][1]);
        Ks[i] = warpSum(k[i][0] + k[i][1]);
    }
    float s_dots = 0.f;
#pragma unroll
    for (int i = 0; i < 8; i++) s_dots = fmaf(Qs[i], Ks[i], s_dots);

    float ss_qr = 0.f, ss_kr = 0.f, ss_dots = 0.f;
    int pr = 0;
#pragma unroll
    for (int i = 0; i < 8; i++)
#pragma unroll
        for (int i2 = i; i2 < 8; i2++) {
            float coef = (i == i2) ? 1.f : 2.f;
            float pq0 = q[i][0] * q[i2][0], pq1 = q[i][1] * q[i2][1];
            float pk0 = k[i][0] * k[i2][0], pk1 = k[i][1] * k[i2][1];
            ss_qr += coef * (pq0 * Ws[pr * 64 + lane] + pq1 * Ws[pr * 64 + lane + 32]);
            ss_kr += coef * (pk0 * Ws[(36 + pr) * 64 + lane] + pk1 * Ws[(36 + pr) * 64 + lane + 32]);
            float gq = warpSum(pq0 + pq1);
            float gk = warpSum(pk0 + pk1);
            ss_dots = fmaf(coef * gq, gk, ss_dots);
            pr++;
        }
    s_qr = warpSum(s_qr); ss_qr = warpSum(ss_qr);
    s_kr = warpSum(s_kr); ss_kr = warpSum(ss_kr);
    if (lane == 0) {
        int base = bb * 24 + h * 3;
        part[(base + 0) * 2] = s_qr;   part[(base + 0) * 2 + 1] = ss_qr;
        part[(base + 1) * 2] = s_kr;   part[(base + 1) * 2 + 1] = ss_kr;
        part[(base + 2) * 2] = s_dots; part[(base + 2) * 2 + 1] = ss_dots;
    }
}

__global__ void __launch_bounds__(256) attA_fin_k(const float* __restrict__ part,
                                                  const float* __restrict__ ga,
                                                  const float* __restrict__ ba,
                                                  float* __restrict__ scA,
                                                  float* __restrict__ shA) {
    int ch = blockIdx.x;
    float s = 0.f, ss = 0.f;
    for (int bb = threadIdx.x; bb < 512; bb += 256) {
        s  += part[(bb * 24 + ch) * 2];
        ss += part[(bb * 24 + ch) * 2 + 1];
    }
    blockReduce2(s, ss);
    if (threadIdx.x == 0) {
        const float invN = 1.0f / 2097152.0f;
        float mean = s * invN;
        float var  = ss * invN - mean * mean;
        float sc = ga[ch] * rsqrtf(var + EPSV);
        scA[ch] = sc;
        shA[ch] = ba[ch] - mean * sc;
    }
}

// ----- attention mainloop: logits (BN'd) -> softmax -> sv & sve -------------
__global__ void __launch_bounds__(256) att_main_k(const float* __restrict__ qkv,
                                                  const float* __restrict__ rel,
                                                  const float* __restrict__ scA,
                                                  const float* __restrict__ shA,
                                                  float* __restrict__ outb) {
    int bb = blockIdx.x >> 3, h = blockIdx.x & 7;
    __shared__ float qs[8][64], ks[8][64], vs[16][64];
    __shared__ float rqs[8][128], rks[8][128], rvs[16][128];
    __shared__ float attn[64][68];
    int tid = threadIdx.x;
    float sc0 = scA[h * 3 + 0], sh0 = shA[h * 3 + 0];
    float sc1 = scA[h * 3 + 1], sh1 = shA[h * 3 + 1];
    float sc2 = scA[h * 3 + 2], sh2 = shA[h * 3 + 2];

    for (int e = tid; e < 2048; e += 256) {
        int r = e >> 6, d = e & 63;
        float v = qkv[(r * 8 + h) * 32768 + bb * 64 + d];
        if (r < 8) qs[r][d] = v;
        else if (r < 16) ks[r - 8][d] = v;
        else vs[r - 16][d] = v;
    }
    for (int e = tid; e < 32 * 127; e += 256) {
        int r = e / 127, p = e % 127;
        float v = rel[e];
        if (r < 8) rqs[r][p] = v * sc0;
        else if (r < 16) rks[r - 8][p] = v * sc1;
        else rvs[r - 16][p] = v;
    }
    if (tid < 16) {
        rvs[tid][127] = 0.f;
        if (tid < 8) { rqs[tid][127] = 0.f; rks[tid][127] = 0.f; }
    }
    __syncthreads();

    // ---- logits: thread owns 4d x 4j tile ----
    {
        int d0 = (tid >> 4) << 2;
        int j0 = (tid & 15) << 2;
        int pb = d0 - j0 + 60;
        float shsum = sh0 + sh1 + sh2;
        float acc[4][4];
#pragma unroll
        for (int a = 0; a < 4; a++)
#pragma unroll
            for (int b = 0; b < 4; b++) acc[a][b] = shsum;
#pragma unroll
        for (int i = 0; i < 8; i++) {
            float4 qv = *(const float4*)&qs[i][d0];
            float4 kv = *(const float4*)&ks[i][d0];
            float4 kj = *(const float4*)&ks[i][j0];
            float r8q[8], r8k[8];
            *(float4*)&r8q[0] = *(const float4*)&rqs[i][pb];
            *(float4*)&r8q[4] = *(const float4*)&rqs[i][pb + 4];
            *(float4*)&r8k[0] = *(const float4*)&rks[i][pb];
            *(float4*)&r8k[4] = *(const float4*)&rks[i][pb + 4];
            float qa[4] = {qv.x, qv.y, qv.z, qv.w};
            float ka[4] = {kv.x, kv.y, kv.z, kv.w};
            float kja[4] = {kj.x, kj.y, kj.z, kj.w};
            float q2[4];
#pragma unroll
            for (int dd = 0; dd < 4; dd++) q2[dd] = qa[dd] * sc2;
#pragma unroll
            for (int dd = 0; dd < 4; dd++)
#pragma unroll
                for (int jj = 0; jj < 4; jj++) {
                    float t = acc[dd][jj];
                    t = fmaf(qa[dd], r8q[3 + dd - jj], t);
                    t = fmaf(ka[dd], r8k[3 + dd - jj], t);
                    t = fmaf(q2[dd], kja[jj], t);
                    acc[dd][jj] = t;
                }
        }
#pragma unroll
        for (int dd = 0; dd < 4; dd++)
            *(float4*)&attn[d0 + dd][j0] = make_float4(acc[dd][0], acc[dd][1], acc[dd][2], acc[dd][3]);
    }
    __syncthreads();

    // ---- softmax ----
    {
        int w = tid >> 5, lane = tid & 31;
        for (int r = 0; r < 8; r++) {
            int d = w * 8 + r;
            float v0 = attn[d][lane], v1 = attn[d][lane + 32];
            float mx = fmaxf(v0, v1);
#pragma unroll
            for (int o = 16; o > 0; o >>= 1) mx = fmaxf(mx, __shfl_xor_sync(0xffffffffu, mx, o));
            float e0 = __expf(v0 - mx), e1 = __expf(v1 - mx);
            float sm = e0 + e1;
#pragma unroll
            for (int o = 16; o > 0; o >>= 1) sm += __shfl_xor_sync(0xffffffffu, sm, o);
            float inv = 1.f / sm;
            attn[d][lane] = e0 * inv;
            attn[d][lane + 32] = e1 * inv;
        }
    }
    __syncthreads();

    // ---- sv & sve: thread owns 4d x 4i, 16 j; reduce over 4 jq lanes ----
    {
        int dg = tid >> 4;
        int ig = (tid >> 2) & 3;
        int jq = tid & 3;
        int d0 = dg << 2, i0 = ig << 2;
        float asv[4][4], asve[4][4];   // [ii][dd]
#pragma unroll
        for (int a = 0; a < 4; a++)
#pragma unroll
            for (int b = 0; b < 4; b++) { asv[a][b] = 0.f; asve[a][b] = 0.f; }

        for (int j4 = jq * 16; j4 < jq * 16 + 16; j4 += 4) {
            float a[4][4];
#pragma unroll
            for (int dd = 0; dd < 4; dd++)
                *(float4*)a[dd] = *(const float4*)&attn[d0 + dd][j4];
            int pb = d0 - j4 + 60;
#pragma unroll
            for (int ii = 0; ii < 4; ii++) {
                int i = i0 + ii;
                float vv[4];
                *(float4*)vv = *(const float4*)&vs[i][j4];
                float r8[8];
                *(float4*)&r8[0] = *(const float4*)&rvs[i][pb];
                *(float4*)&r8[4] = *(const float4*)&rvs[i][pb + 4];
#pragma unroll
                for (int dd = 0; dd < 4; dd++)
#pragma unroll
                    for (int jj = 0; jj < 4; jj++) {
                        asv[ii][dd]  = fmaf(a[dd][jj], vv[jj], asv[ii][dd]);
                        asve[ii][dd] = fmaf(a[dd][jj], r8[3 + dd - jj], asve[ii][dd]);
                    }
            }
        }
#pragma unroll
        for (int ii = 0; ii < 4; ii++)
#pragma unroll
            for (int dd = 0; dd < 4; dd++) {
                asv[ii][dd]  += __shfl_xor_sync(0xffffffffu, asv[ii][dd], 1);
                asv[ii][dd]  += __shfl_xor_sync(0xffffffffu, asv[ii][dd], 2);
                asve[ii][dd] += __shfl_xor_sync(0xffffffffu, asve[ii][dd], 1);
                asve[ii][dd] += __shfl_xor_sync(0xffffffffu, asve[ii][dd], 2);
            }
        if (jq == 0) {
#pragma unroll
            for (int ii = 0; ii < 4; ii++) {
                int c2 = h * 16 + i0 + ii;
                size_t o0 = ((size_t)bb * 128 + c2) * 64 + d0;
                *(float4*)&outb[o0] = make_float4(asve[ii][0], asve[ii][1], asve[ii][2], asve[ii][3]);
                *(float4*)&outb[o0 + (size_t)512 * 128 * 64] =
                    make_float4(asv[ii][0], asv[ii][1], asv[ii][2], asv[ii][3]);
            }
        }
    }
}

// ----- T2: BN + sum over s + transpose -> x2[c2][(b*64+h)*64+w] --------------
__global__ void __launch_bounds__(256) t2_k(const float* __restrict__ outb,
                                            const float* __restrict__ sc,
                                            const float* __restrict__ sh,
                                            float* __restrict__ x2) {
    __shared__ float tile[64][65];
    int c2 = blockIdx.x, b = blockIdx.y;
    float s0 = sc[c2],       h0 = sh[c2];
    float s1 = sc[128 + c2], h1 = sh[128 + c2];
    const float* base0 = outb + ((size_t)(b * 64) * 128 + c2) * 64;
    const float* base1 = base0 + (size_t)512 * 128 * 64;
    for (int e = threadIdx.x; e < 4096; e += 256) {
        int w = e >> 6, h = e & 63;
        float v = fmaf(base0[w * 8192 + h], s0, h0) + fmaf(base1[w * 8192 + h], s1, h1);
        tile[h][w] = v;
    }
    __syncthreads();
    float* dst = x2 + (size_t)c2 * 32768 + b * 4096;
    for (int e = threadIdx.x; e < 4096; e += 256) {
        int h = e >> 6, w = e & 63;
        dst[e] = tile[h][w];
    }
}

// ----- T3: BN + sum over s + relu -> x3[b][c2][h][w] -------------------------
__global__ void __launch_bounds__(256) t3_k(const float* __restrict__ outb,
                                            const float* __restrict__ sc,
                                            const float* __restrict__ sh,
                                            float* __restrict__ x3) {
    int g = blockIdx.x * 256 + threadIdx.x;
    int w  = g & 63;
    int r  = g >> 6;
    int h  = r & 63;
    int c2 = (r >> 6) & 127;
    int b  = r >> 13;
    int bb = b * 64 + h;
    float v = fmaf(outb[(bb * 128 + c2) * 64 + w], sc[c2], sh[c2])
            + fmaf(outb[((512 + bb) * 128 + c2) * 64 + w], sc[128 + c2], sh[128 + c2]);
    x3[g] = fmaxf(v, 0.f);
}

// ----- final: y = relu(bn(conv_out) + x_in) ----------------------------------
__global__ void __launch_bounds__(256) final_k(const float* __restrict__ co,
                                               const float* __restrict__ sc,
                                               const float* __restrict__ sh,
                                               const float* __restrict__ x_in,
                                               float* __restrict__ out) {
    int g = blockIdx.x * 256 + threadIdx.x;
    int o  = (g >> 12) & 255;
    int b  = g >> 20;
    int hw = g & 4095;
    float v = fmaf(co[o * 32768 + b * 4096 + hw], sc[o], sh[o]) + x_in[g];
    out[g] = fmaxf(v, 0.f);
}

// ---------------------------------------------------------------------------
extern "C" void kernel_launch(void* const* d_in, const int* in_sizes, int n_in,
                              void* d_out, int out_size) {
    const float* x_in   = (const float*)d_in[0];
    const float* w_in   = (const float*)d_in[1];
    const float* g_in   = (const float*)d_in[2];
    const float* b_in   = (const float*)d_in[3];
    const float* w_out  = (const float*)d_in[4];
    const float* gout   = (const float*)d_in[5];
    const float* bout   = (const float*)d_in[6];
    const float* wqkv_h = (const float*)d_in[7];
    const float* rel_h  = (const float*)d_in[8];
    const float* ga_h   = (const float*)d_in[9];
    const float* ba_h   = (const float*)d_in[10];
    const float* go_h   = (const float*)d_in[11];
    const float* bo_h   = (const float*)d_in[12];
    const float* wqkv_w = (const float*)d_in[13];
    const float* rel_w  = (const float*)d_in[14];
    const float* ga_w   = (const float*)d_in[15];
    const float* ba_w   = (const float*)d_in[16];
    const float* go_w   = (const float*)d_in[17];
    const float* bo_w   = (const float*)d_in[18];
    float* out = (float*)d_out;

    float *conv1, *x1, *qkv, *outb, *x2, *x3, *co, *part, *sum, *sc, *sh, *scA, *shA, *Wt, *St;
    cudaGetSymbolAddress((void**)&conv1, g_conv1);
    cudaGetSymbolAddress((void**)&x1,    g_x1);
    cudaGetSymbolAddress((void**)&qkv,   g_qkv);
    cudaGetSymbolAddress((void**)&outb,  g_outb);
    cudaGetSymbolAddress((void**)&x2,    g_x2);
    cudaGetSymbolAddress((void**)&x3,    g_x3);
    cudaGetSymbolAddress((void**)&co,    g_co);
    cudaGetSymbolAddress((void**)&part,  g_part);
    cudaGetSymbolAddress((void**)&sum,   g_sum);
    cudaGetSymbolAddress((void**)&sc,    g_sc);
    cudaGetSymbolAddress((void**)&sh,    g_sh);
    cudaGetSymbolAddress((void**)&scA,   g_scA);
    cudaGetSymbolAddress((void**)&shA,   g_shA);
    cudaGetSymbolAddress((void**)&Wt,    g_Wt);
    cudaGetSymbolAddress((void**)&St,    g_St);

    const float invTok = 1.0f / 32768.0f;

    // conv_in
    gemm_k<1><<<dim3(256, 1), 256>>>(w_in, x_in, conv1, 128, 32768, 256);
    reduce_rows_k<<<128, 256>>>(conv1, 32768, sum);
    finalize_k<<<1, 256>>>(sum, g_in, b_in, 128, invTok, sc, sh);
    t1_k<<<dim3(128, 8), 256>>>(conv1, sc, sh, x1);

    // axial attention along H
    gemm_k<0><<<dim3(256, 2), 256>>>(wqkv_h, x1, qkv, 256, 32768, 128);
    rel_prep_k<<<1, 128>>>(rel_h, Wt, St);
    att_stats_k<<<512, 256>>>(qkv, Wt, St, part);
    attA_fin_k<<<24, 256>>>(part, ga_h, ba_h, scA, shA);
    att_main_k<<<4096, 256>>>(qkv, rel_h, scA, shA, outb);
    reduce_outb_k<<<256, 256>>>(outb, sum);
    finalize_k<<<1, 256>>>(sum, go_h, bo_h, 256, invTok, sc, sh);
    t2_k<<<dim3(128, 8), 256>>>(outb, sc, sh, x2);

    // axial attention along W
    gemm_k<0><<<dim3(256, 2), 256>>>(wqkv_w, x2, qkv, 256, 32768, 128);
    rel_prep_k<<<1, 128>>>(rel_w, Wt, St);
    att_stats_k<<<512, 256>>>(qkv, Wt, St, part);
    attA_fin_k<<<24, 256>>>(part, ga_w, ba_w, scA, shA);
    att_main_k<<<4096, 256>>>(qkv, rel_w, scA, shA, outb);
    reduce_outb_k<<<256, 256>>>(outb, sum);
    finalize_k<<<1, 256>>>(sum, go_w, bo_w, 256, invTok, sc, sh);
    t3_k<<<16384, 256>>>(outb, sc, sh, x3);

    // conv_out + BN + residual + relu
    gemm_k<1><<<dim3(256, 2), 256>>>(w_out, x3, co, 256, 32768, 128);
    reduce_rows_k<<<256, 256>>>(co, 32768, sum);
    finalize_k<<<1, 256>>>(sum, gout, bout, 256, invTok, sc, sh);
    final_k<<<32768, 256>>>(co, sc, sh, x_in, out);
}

// round 5
// speedup vs baseline: 1.3159x; 1.1556x over previous
#include <cuda_runtime.h>
#include <cuda_bf16.h>
#include <cstdint>

// ---------------------------------------------------------------------------
// Problem constants: B=8, C_IN=256, DIM=64, HEADS=8, D_IN=128, DKQ=8, DV=16
// ---------------------------------------------------------------------------
#define EPSV 1e-5f

// ------------------------- scratch (global, static) ------------------------
__device__ float g_conv1[128 * 32768];
__device__ float g_x1  [128 * 32768];
__device__ float g_qkv [256 * 32768];
__device__ float g_outb[2 * 512 * 128 * 64];
__device__ float g_x2  [128 * 32768];
__device__ float g_x3  [128 * 32768];
__device__ float g_co  [256 * 32768];
__device__ float g_part[512 * 24 * 2];
__device__ float g_sum [512];
__device__ float g_sc  [256];
__device__ float g_sh  [256];
__device__ float g_scA [24];
__device__ float g_shA [24];
__device__ float g_Wt  [72 * 64];
__device__ float g_St  [16 * 64];

// ========================= warp-MMA helpers (sm_80+) ========================
__device__ __forceinline__ uint32_t smem_u32(const void* p) {
    uint32_t a;
    asm("{ .reg .u64 t; cvta.to.shared.u64 t, %1; cvt.u32.u64 %0, t; }" : "=r"(a) : "l"(p));
    return a;
}
__device__ __forceinline__ void ldsm_x4(uint32_t (&r)[4], uint32_t addr) {
    asm volatile("ldmatrix.sync.aligned.m8n8.x4.shared.b16 {%0,%1,%2,%3}, [%4];"
                 : "=r"(r[0]), "=r"(r[1]), "=r"(r[2]), "=r"(r[3]) : "r"(addr));
}
__device__ __forceinline__ void ldsm_x4t(uint32_t (&r)[4], uint32_t addr) {
    asm volatile("ldmatrix.sync.aligned.m8n8.x4.trans.shared.b16 {%0,%1,%2,%3}, [%4];"
                 : "=r"(r[0]), "=r"(r[1]), "=r"(r[2]), "=r"(r[3]) : "r"(addr));
}
__device__ __forceinline__ void mma_bf16(float (&c)[4], const uint32_t (&a)[4],
                                         uint32_t b0, uint32_t b1) {
    asm volatile("mma.sync.aligned.m16n8k16.row.col.f32.bf16.bf16.f32 "
                 "{%0,%1,%2,%3}, {%4,%5,%6,%7}, {%8,%9}, {%0,%1,%2,%3};"
                 : "+f"(c[0]), "+f"(c[1]), "+f"(c[2]), "+f"(c[3])
                 : "r"(a[0]), "r"(a[1]), "r"(a[2]), "r"(a[3]), "r"(b0), "r"(b1));
}
__device__ __forceinline__ uint32_t pack_hilo(float x, float y, uint32_t& lo) {
    __nv_bfloat162 h = __floats2bfloat162_rn(x, y);
    float rx = x - __bfloat162float(h.x);
    float ry = y - __bfloat162float(h.y);
    __nv_bfloat162 l = __floats2bfloat162_rn(rx, ry);
    lo = *reinterpret_cast<uint32_t*>(&l);
    return *reinterpret_cast<uint32_t*>(&h);
}

// ======================= tensor-core GEMM (bf16 split) ======================
// C[M][32768] = A[M][K] * B[K][32768], fp32 in/out.
// MODE 0: B row-major [K][32768].  MODE 1: B = [b][K][4096], n = b*4096+hw.
// Block 128x128, 8 warps (4m x 2n), warp tile 32x64, BK=64.
// Smem halves layout (padded, conflict-free ldmatrix):
//   Ah[128][72], Al[128][72], Bh[64][136], Bl[64][136]
template <int KDIM, int MODE>
__global__ void __launch_bounds__(256) gemm_mma(const float* __restrict__ A,
                                                const float* __restrict__ Bm,
                                                float* __restrict__ C) {
    constexpr uint32_t AL_B = 128 * 72 * 2;        // 18432
    constexpr uint32_t BH_B = 2 * AL_B;            // 36864
    constexpr uint32_t BL_B = BH_B + 64 * 136 * 2; // 54272

    extern __shared__ __align__(16) char smem[];
    __nv_bfloat16* sAh = (__nv_bfloat16*)smem;
    __nv_bfloat16* sAl = (__nv_bfloat16*)(smem + AL_B);
    __nv_bfloat16* sBh = (__nv_bfloat16*)(smem + BH_B);
    __nv_bfloat16* sBl = (__nv_bfloat16*)(smem + BL_B);
    uint32_t sbase = smem_u32(smem);

    int tid = threadIdx.x, lane = tid & 31, wid = tid >> 5;
    int warp_m = wid & 3, warp_n = wid >> 2;
    int bn = blockIdx.x * 128;
    int bm = blockIdx.y * 128;

    // ldmatrix lane address components
    int a_row_off = ((lane >> 3) & 1) * 8 + (lane & 7);
    int a_k_off   = (lane >> 4) * 8;
    int b_k_off   = a_row_off;
    int b_n_off   = a_k_off;

    float acc[2][8][4];
#pragma unroll
    for (int mt = 0; mt < 2; mt++)
#pragma unroll
        for (int nt = 0; nt < 8; nt++)
#pragma unroll
            for (int r = 0; r < 4; r++) acc[mt][nt][r] = 0.f;

    // A fill indices: 2 threads/row, 8 float4 each
    int aRow = tid >> 1, aQ = (tid & 1) * 32;
    // B fill indices: 4 threads/row, 8 float4 each
    int bRow = tid >> 2, bQ = (tid & 3) * 32;

    for (int k0 = 0; k0 < KDIM; k0 += 64) {
        // ---- A chunk: fp32 -> hi/lo bf16 ----
        {
            const float* ar = A + (size_t)(bm + aRow) * KDIM + k0 + aQ;
            uint32_t off = (uint32_t)(aRow * 72 + aQ);
#pragma unroll
            for (int i = 0; i < 8; i++) {
                float4 v = *(const float4*)(ar + i * 4);
                uint32_t l0, l1;
                uint32_t h0 = pack_hilo(v.x, v.y, l0);
                uint32_t h1 = pack_hilo(v.z, v.w, l1);
                *(uint2*)(sAh + off + i * 4) = make_uint2(h0, h1);
                *(uint2*)(sAl + off + i * 4) = make_uint2(l0, l1);
            }
        }
        // ---- B chunk ----
        {
            const float* br = (MODE == 0)
                ? Bm + (size_t)(k0 + bRow) * 32768 + bn + bQ
                : Bm + ((size_t)(bn >> 12) * KDIM + k0 + bRow) * 4096 + (bn & 4095) + bQ;
            uint32_t off = (uint32_t)(bRow * 136 + bQ);
#pragma unroll
            for (int i = 0; i < 8; i++) {
                float4 v = *(const float4*)(br + i * 4);
                uint32_t l0, l1;
                uint32_t h0 = pack_hilo(v.x, v.y, l0);
                uint32_t h1 = pack_hilo(v.z, v.w, l1);
                *(uint2*)(sBh + off + i * 4) = make_uint2(h0, h1);
                *(uint2*)(sBl + off + i * 4) = make_uint2(l0, l1);
            }
        }
        __syncthreads();

        // ---- MMA over 4 k16-steps ----
#pragma unroll
        for (int ks = 0; ks < 4; ks++) {
            uint32_t ah[2][4], al[2][4], bh[4][4], bl[4][4];
#pragma unroll
            for (int mt = 0; mt < 2; mt++) {
                uint32_t addr = sbase +
                    (uint32_t)(((warp_m * 32 + mt * 16 + a_row_off) * 72 + ks * 16 + a_k_off) * 2);
                ldsm_x4(ah[mt], addr);
                ldsm_x4(al[mt], addr + AL_B);
            }
#pragma unroll
            for (int gi = 0; gi < 4; gi++) {
                uint32_t addr = sbase + BH_B +
                    (uint32_t)(((ks * 16 + b_k_off) * 136 + warp_n * 64 + gi * 16 + b_n_off) * 2);
                ldsm_x4t(bh[gi], addr);
                ldsm_x4t(bl[gi], addr + (BL_B - BH_B));
            }
#pragma unroll
            for (int mt = 0; mt < 2; mt++)
#pragma unroll
                for (int gi = 0; gi < 4; gi++)
#pragma unroll
                    for (int sub = 0; sub < 2; sub++) {
                        int nt = gi * 2 + sub;
                        mma_bf16(acc[mt][nt], ah[mt], bh[gi][2 * sub], bh[gi][2 * sub + 1]);
                        mma_bf16(acc[mt][nt], ah[mt], bl[gi][2 * sub], bl[gi][2 * sub + 1]);
                        mma_bf16(acc[mt][nt], al[mt], bh[gi][2 * sub], bh[gi][2 * sub + 1]);
                    }
        }
        __syncthreads();
    }

    // ---- epilogue ----
    int g = lane >> 2, t = lane & 3;
#pragma unroll
    for (int mt = 0; mt < 2; mt++) {
        int r0 = bm + warp_m * 32 + mt * 16 + g;
#pragma unroll
        for (int nt = 0; nt < 8; nt++) {
            int col = bn + warp_n * 64 + nt * 8 + 2 * t;
            *(float2*)(C + (size_t)r0 * 32768 + col) = make_float2(acc[mt][nt][0], acc[mt][nt][1]);
            *(float2*)(C + (size_t)(r0 + 8) * 32768 + col) = make_float2(acc[mt][nt][2], acc[mt][nt][3]);
        }
    }
}

// ------------------------------ helpers ------------------------------------
__device__ __forceinline__ float warpSum(float v) {
#pragma unroll
    for (int o = 16; o > 0; o >>= 1) v += __shfl_xor_sync(0xffffffffu, v, o);
    return v;
}
__device__ __forceinline__ void blockReduce2(float& a, float& b) {
    __shared__ float sa[8], sb2[8];
    int lane = threadIdx.x & 31, w = threadIdx.x >> 5;
#pragma unroll
    for (int o = 16; o > 0; o >>= 1) {
        a += __shfl_xor_sync(0xffffffffu, a, o);
        b += __shfl_xor_sync(0xffffffffu, b, o);
    }
    if (lane == 0) { sa[w] = a; sb2[w] = b; }
    __syncthreads();
    a = (threadIdx.x < 8) ? sa[threadIdx.x] : 0.f;
    b = (threadIdx.x < 8) ? sb2[threadIdx.x] : 0.f;
    if (w == 0) {
#pragma unroll
        for (int o = 4; o > 0; o >>= 1) {
            a += __shfl_xor_sync(0xffffffffu, a, o);
            b += __shfl_xor_sync(0xffffffffu, b, o);
        }
    }
}

// ---------------------- per-channel sum/sumsq -------------------------------
__global__ void __launch_bounds__(256) reduce_rows_k(const float* __restrict__ src,
                                                     int rowlen, float* __restrict__ out) {
    int ch = blockIdx.x;
    const float* p = src + (size_t)ch * rowlen;
    float s = 0.f, ss = 0.f;
    for (int i = threadIdx.x * 4; i < rowlen; i += 1024) {
        float4 v = *(const float4*)(p + i);
        s += v.x + v.y + v.z + v.w;
        ss = fmaf(v.x, v.x, ss); ss = fmaf(v.y, v.y, ss);
        ss = fmaf(v.z, v.z, ss); ss = fmaf(v.w, v.w, ss);
    }
    blockReduce2(s, ss);
    if (threadIdx.x == 0) { out[ch * 2] = s; out[ch * 2 + 1] = ss; }
}

__global__ void __launch_bounds__(256) reduce_outb_k(const float* __restrict__ outb,
                                                     float* __restrict__ out) {
    int ch = blockIdx.x;
    int s_ = ch >> 7, c2 = ch & 127;
    const float* base = outb + ((size_t)s_ * 512 * 128 + c2) * 64;
    float s = 0.f, ss = 0.f;
    for (int t = threadIdx.x; t < 512 * 64; t += 256) {
        int bb = t >> 6, d = t & 63;
        float v = base[bb * 8192 + d];
        s += v; ss = fmaf(v, v, ss);
    }
    blockReduce2(s, ss);
    if (threadIdx.x == 0) { out[ch * 2] = s; out[ch * 2 + 1] = ss; }
}

__global__ void finalize_k(const float* __restrict__ sums, const float* __restrict__ gamma,
                           const float* __restrict__ beta, int nchan, float invN,
                           float* __restrict__ sc, float* __restrict__ sh) {
    int c = blockIdx.x * blockDim.x + threadIdx.x;
    if (c < nchan) {
        float mean = sums[c * 2] * invN;
        float var  = sums[c * 2 + 1] * invN - mean * mean;
        float s = gamma[c] * rsqrtf(var + EPSV);
        sc[c] = s;
        sh[c] = beta[c] - mean * s;
    }
}

// ----- T1: bn+relu + transpose -> x1[o][(b*64+w)*64 + h] ---------------------
__global__ void __launch_bounds__(256) t1_k(const float* __restrict__ conv1,
                                            const float* __restrict__ sc,
                                            const float* __restrict__ sh,
                                            float* __restrict__ x1) {
    __shared__ float tile[64][65];
    int o = blockIdx.x, b = blockIdx.y;
    float s = sc[o], t = sh[o];
    const float* src = conv1 + (size_t)o * 32768 + b * 4096;
    float* dst = x1 + (size_t)o * 32768 + b * 4096;
    for (int e = threadIdx.x; e < 4096; e += 256) {
        int h = e >> 6, w = e & 63;
        tile[w][h] = fmaxf(fmaf(src[e], s, t), 0.f);
    }
    __syncthreads();
    for (int e = threadIdx.x; e < 4096; e += 256) {
        int w = e >> 6, h = e & 63;
        dst[e] = tile[w][h];
    }
}

// ----- rel prep: windowed correlation + window-sum tables --------------------
__global__ void rel_prep_k(const float* __restrict__ rel,
                           float* __restrict__ W, float* __restrict__ S) {
    int t = threadIdx.x;
    if (t < 72) {
        int grp = (t < 36) ? 0 : 1;
        int pr  = (t < 36) ? t : t - 36;
        int i = 0, r = pr;
        while (r >= 8 - i) { r -= 8 - i; i++; }
        int i2 = i + r;
        const float* ra = rel + (grp * 8 + i)  * 127;
        const float* rb = rel + (grp * 8 + i2) * 127;
        float w = 0.f;
        for (int p = 0; p < 64; p++) w = fmaf(ra[p], rb[p], w);
        W[t * 64 + 0] = w;
        for (int d = 1; d < 64; d++) {
            w += ra[d + 63] * rb[d + 63] - ra[d - 1] * rb[d - 1];
            W[t * 64 + d] = w;
        }
    } else if (t < 88) {
        int rr = t - 72;
        const float* ra = rel + rr * 127;
        float s = 0.f;
        for (int p = 0; p < 64; p++) s += ra[p];
        S[rr * 64 + 0] = s;
        for (int d = 1; d < 64; d++) { s += ra[d + 63] - ra[d - 1]; S[rr * 64 + d] = s; }
    }
}

// ----- closed-form attention BN stats ----------------------------------------
__global__ void __launch_bounds__(256) att_stats_k(const float* __restrict__ qkv,
                                                   const float* __restrict__ Wt,
                                                   const float* __restrict__ St,
                                                   float* __restrict__ part) {
    __shared__ float Ws[72 * 64];
    __shared__ float Ss[16 * 64];
    int bb = blockIdx.x;
    int tid = threadIdx.x;
    for (int e = tid; e < 72 * 64; e += 256) Ws[e] = Wt[e];
    for (int e = tid; e < 16 * 64; e += 256) Ss[e] = St[e];
    __syncthreads();
    int h = tid >> 5, lane = tid & 31;
    float q[8][2], k[8][2];
#pragma unroll
    for (int i = 0; i < 8; i++) {
        const float* pq = qkv + (size_t)(i * 8 + h) * 32768 + bb * 64;
        const float* pk = qkv + (size_t)((8 + i) * 8 + h) * 32768 + bb * 64;
        q[i][0] = pq[lane]; q[i][1] = pq[lane + 32];
        k[i][0] = pk[lane]; k[i][1] = pk[lane + 32];
    }
    float s_qr = 0.f, s_kr = 0.f;
    float Qs[8], Ks[8];
#pragma unroll
    for (int i = 0; i < 8; i++) {
        s_qr = fmaf(q[i][0], Ss[i * 64 + lane], s_qr);
        s_qr = fmaf(q[i][1], Ss[i * 64 + lane + 32], s_qr);
        s_kr = fmaf(k[i][0], Ss[(8 + i) * 64 + lane], s_kr);
        s_kr = fmaf(k[i][1], Ss[(8 + i) * 64 + lane + 32], s_kr);
        Qs[i] = warpSum(q[i][0] + q[i][1]);
        Ks[i] = warpSum(k[i][0] + k[i][1]);
    }
    float s_dots = 0.f;
#pragma unroll
    for (int i = 0; i < 8; i++) s_dots = fmaf(Qs[i], Ks[i], s_dots);

    float ss_qr = 0.f, ss_kr = 0.f, ss_dots = 0.f;
    int pr = 0;
#pragma unroll
    for (int i = 0; i < 8; i++)
#pragma unroll
        for (int i2 = i; i2 < 8; i2++) {
            float coef = (i == i2) ? 1.f : 2.f;
            float pq0 = q[i][0] * q[i2][0], pq1 = q[i][1] * q[i2][1];
            float pk0 = k[i][0] * k[i2][0], pk1 = k[i][1] * k[i2][1];
            ss_qr += coef * (pq0 * Ws[pr * 64 + lane] + pq1 * Ws[pr * 64 + lane + 32]);
            ss_kr += coef * (pk0 * Ws[(36 + pr) * 64 + lane] + pk1 * Ws[(36 + pr) * 64 + lane + 32]);
            float gq = warpSum(pq0 + pq1);
            float gk = warpSum(pk0 + pk1);
            ss_dots = fmaf(coef * gq, gk, ss_dots);
            pr++;
        }
    s_qr = warpSum(s_qr); ss_qr = warpSum(ss_qr);
    s_kr = warpSum(s_kr); ss_kr = warpSum(ss_kr);
    if (lane == 0) {
        int base = bb * 24 + h * 3;
        part[(base + 0) * 2] = s_qr;   part[(base + 0) * 2 + 1] = ss_qr;
        part[(base + 1) * 2] = s_kr;   part[(base + 1) * 2 + 1] = ss_kr;
        part[(base + 2) * 2] = s_dots; part[(base + 2) * 2 + 1] = ss_dots;
    }
}

__global__ void __launch_bounds__(256) attA_fin_k(const float* __restrict__ part,
                                                  const float* __restrict__ ga,
                                                  const float* __restrict__ ba,
                                                  float* __restrict__ scA,
                                                  float* __restrict__ shA) {
    int ch = blockIdx.x;
    float s = 0.f, ss = 0.f;
    for (int bb = threadIdx.x; bb < 512; bb += 256) {
        s  += part[(bb * 24 + ch) * 2];
        ss += part[(bb * 24 + ch) * 2 + 1];
    }
    blockReduce2(s, ss);
    if (threadIdx.x == 0) {
        const float invN = 1.0f / 2097152.0f;
        float mean = s * invN;
        float var  = ss * invN - mean * mean;
        float sc = ga[ch] * rsqrtf(var + EPSV);
        scA[ch] = sc;
        shA[ch] = ba[ch] - mean * sc;
    }
}

// ----- attention mainloop ----------------------------------------------------
__global__ void __launch_bounds__(256) att_main_k(const float* __restrict__ qkv,
                                                  const float* __restrict__ rel,
                                                  const float* __restrict__ scA,
                                                  const float* __restrict__ shA,
                                                  float* __restrict__ outb) {
    int bb = blockIdx.x >> 3, h = blockIdx.x & 7;
    __shared__ float qs[8][64], ks[8][64], vs[16][64];
    __shared__ float rqs[8][128], rks[8][128], rvs[16][128];
    __shared__ float attn[64][68];
    int tid = threadIdx.x;
    float sc0 = scA[h * 3 + 0], sh0 = shA[h * 3 + 0];
    float sc1 = scA[h * 3 + 1], sh1 = shA[h * 3 + 1];
    float sc2 = scA[h * 3 + 2], sh2 = shA[h * 3 + 2];

    for (int e = tid; e < 2048; e += 256) {
        int r = e >> 6, d = e & 63;
        float v = qkv[(r * 8 + h) * 32768 + bb * 64 + d];
        if (r < 8) qs[r][d] = v;
        else if (r < 16) ks[r - 8][d] = v;
        else vs[r - 16][d] = v;
    }
    for (int e = tid; e < 32 * 127; e += 256) {
        int r = e / 127, p = e % 127;
        float v = rel[e];
        if (r < 8) rqs[r][p] = v * sc0;
        else if (r < 16) rks[r - 8][p] = v * sc1;
        else rvs[r - 16][p] = v;
    }
    if (tid < 16) {
        rvs[tid][127] = 0.f;
        if (tid < 8) { rqs[tid][127] = 0.f; rks[tid][127] = 0.f; }
    }
    __syncthreads();

    {
        int d0 = (tid >> 4) << 2;
        int j0 = (tid & 15) << 2;
        int pb = d0 - j0 + 60;
        float shsum = sh0 + sh1 + sh2;
        float acc[4][4];
#pragma unroll
        for (int a = 0; a < 4; a++)
#pragma unroll
            for (int b = 0; b < 4; b++) acc[a][b] = shsum;
#pragma unroll
        for (int i = 0; i < 8; i++) {
            float4 qv = *(const float4*)&qs[i][d0];
            float4 kv = *(const float4*)&ks[i][d0];
            float4 kj = *(const float4*)&ks[i][j0];
            float r8q[8], r8k[8];
            *(float4*)&r8q[0] = *(const float4*)&rqs[i][pb];
            *(float4*)&r8q[4] = *(const float4*)&rqs[i][pb + 4];
            *(float4*)&r8k[0] = *(const float4*)&rks[i][pb];
            *(float4*)&r8k[4] = *(const float4*)&rks[i][pb + 4];
            float qa[4] = {qv.x, qv.y, qv.z, qv.w};
            float ka[4] = {kv.x, kv.y, kv.z, kv.w};
            float kja[4] = {kj.x, kj.y, kj.z, kj.w};
            float q2[4];
#pragma unroll
            for (int dd = 0; dd < 4; dd++) q2[dd] = qa[dd] * sc2;
#pragma unroll
            for (int dd = 0; dd < 4; dd++)
#pragma unroll
                for (int jj = 0; jj < 4; jj++) {
                    float t = acc[dd][jj];
                    t = fmaf(qa[dd], r8q[3 + dd - jj], t);
                    t = fmaf(ka[dd], r8k[3 + dd - jj], t);
                    t = fmaf(q2[dd], kja[jj], t);
                    acc[dd][jj] = t;
                }
        }
#pragma unroll
        for (int dd = 0; dd < 4; dd++)
            *(float4*)&attn[d0 + dd][j0] = make_float4(acc[dd][0], acc[dd][1], acc[dd][2], acc[dd][3]);
    }
    __syncthreads();

    {
        int w = tid >> 5, lane = tid & 31;
        for (int r = 0; r < 8; r++) {
            int d = w * 8 + r;
            float v0 = attn[d][lane], v1 = attn[d][lane + 32];
            float mx = fmaxf(v0, v1);
#pragma unroll
            for (int o = 16; o > 0; o >>= 1) mx = fmaxf(mx, __shfl_xor_sync(0xffffffffu, mx, o));
            float e0 = __expf(v0 - mx), e1 = __expf(v1 - mx);
            float sm = e0 + e1;
#pragma unroll
            for (int o = 16; o > 0; o >>= 1) sm += __shfl_xor_sync(0xffffffffu, sm, o);
            float inv = 1.f / sm;
            attn[d][lane] = e0 * inv;
            attn[d][lane + 32] = e1 * inv;
        }
    }
    __syncthreads();

    {
        int dg = tid >> 4;
        int ig = (tid >> 2) & 3;
        int jq = tid & 3;
        int d0 = dg << 2, i0 = ig << 2;
        float asv[4][4], asve[4][4];
#pragma unroll
        for (int a = 0; a < 4; a++)
#pragma unroll
            for (int b = 0; b < 4; b++) { asv[a][b] = 0.f; asve[a][b] = 0.f; }

        for (int j4 = jq * 16; j4 < jq * 16 + 16; j4 += 4) {
            float a[4][4];
#pragma unroll
            for (int dd = 0; dd < 4; dd++)
                *(float4*)a[dd] = *(const float4*)&attn[d0 + dd][j4];
            int pb = d0 - j4 + 60;
#pragma unroll
            for (int ii = 0; ii < 4; ii++) {
                int i = i0 + ii;
                float vv[4];
                *(float4*)vv = *(const float4*)&vs[i][j4];
                float r8[8];
                *(float4*)&r8[0] = *(const float4*)&rvs[i][pb];
                *(float4*)&r8[4] = *(const float4*)&rvs[i][pb + 4];
#pragma unroll
                for (int dd = 0; dd < 4; dd++)
#pragma unroll
                    for (int jj = 0; jj < 4; jj++) {
                        asv[ii][dd]  = fmaf(a[dd][jj], vv[jj], asv[ii][dd]);
                        asve[ii][dd] = fmaf(a[dd][jj], r8[3 + dd - jj], asve[ii][dd]);
                    }
            }
        }
#pragma unroll
        for (int ii = 0; ii < 4; ii++)
#pragma unroll
            for (int dd = 0; dd < 4; dd++) {
                asv[ii][dd]  += __shfl_xor_sync(0xffffffffu, asv[ii][dd], 1);
                asv[ii][dd]  += __shfl_xor_sync(0xffffffffu, asv[ii][dd], 2);
                asve[ii][dd] += __shfl_xor_sync(0xffffffffu, asve[ii][dd], 1);
                asve[ii][dd] += __shfl_xor_sync(0xffffffffu, asve[ii][dd], 2);
            }
        if (jq == 0) {
#pragma unroll
            for (int ii = 0; ii < 4; ii++) {
                int c2 = h * 16 + i0 + ii;
                size_t o0 = ((size_t)bb * 128 + c2) * 64 + d0;
                *(float4*)&outb[o0] = make_float4(asve[ii][0], asve[ii][1], asve[ii][2], asve[ii][3]);
                *(float4*)&outb[o0 + (size_t)512 * 128 * 64] =
                    make_float4(asv[ii][0], asv[ii][1], asv[ii][2], asv[ii][3]);
            }
        }
    }
}

// ----- T2: BN + sum over s + transpose -> x2[c2][(b*64+h)*64+w] --------------
__global__ void __launch_bounds__(256) t2_k(const float* __restrict__ outb,
                                            const float* __restrict__ sc,
                                            const float* __restrict__ sh,
                                            float* __restrict__ x2) {
    __shared__ float tile[64][65];
    int c2 = blockIdx.x, b = blockIdx.y;
    float s0 = sc[c2],       h0 = sh[c2];
    float s1 = sc[128 + c2], h1 = sh[128 + c2];
    const float* base0 = outb + ((size_t)(b * 64) * 128 + c2) * 64;
    const float* base1 = base0 + (size_t)512 * 128 * 64;
    for (int e = threadIdx.x; e < 4096; e += 256) {
        int w = e >> 6, h = e & 63;
        float v = fmaf(base0[w * 8192 + h], s0, h0) + fmaf(base1[w * 8192 + h], s1, h1);
        tile[h][w] = v;
    }
    __syncthreads();
    float* dst = x2 + (size_t)c2 * 32768 + b * 4096;
    for (int e = threadIdx.x; e < 4096; e += 256) {
        int h = e >> 6, w = e & 63;
        dst[e] = tile[h][w];
    }
}

// ----- T3 ---------------------------------------------------------------------
__global__ void __launch_bounds__(256) t3_k(const float* __restrict__ outb,
                                            const float* __restrict__ sc,
                                            const float* __restrict__ sh,
                                            float* __restrict__ x3) {
    int g = blockIdx.x * 256 + threadIdx.x;
    int w  = g & 63;
    int r  = g >> 6;
    int h  = r & 63;
    int c2 = (r >> 6) & 127;
    int b  = r >> 13;
    int bb = b * 64 + h;
    float v = fmaf(outb[(bb * 128 + c2) * 64 + w], sc[c2], sh[c2])
            + fmaf(outb[((512 + bb) * 128 + c2) * 64 + w], sc[128 + c2], sh[128 + c2]);
    x3[g] = fmaxf(v, 0.f);
}

// ----- final -------------------------------------------------------------------
__global__ void __launch_bounds__(256) final_k(const float* __restrict__ co,
                                               const float* __restrict__ sc,
                                               const float* __restrict__ sh,
                                               const float* __restrict__ x_in,
                                               float* __restrict__ out) {
    int g = blockIdx.x * 256 + threadIdx.x;
    int o  = (g >> 12) & 255;
    int b  = g >> 20;
    int hw = g & 4095;
    float v = fmaf(co[o * 32768 + b * 4096 + hw], sc[o], sh[o]) + x_in[g];
    out[g] = fmaxf(v, 0.f);
}

// ---------------------------------------------------------------------------
extern "C" void kernel_launch(void* const* d_in, const int* in_sizes, int n_in,
                              void* d_out, int out_size) {
    const float* x_in   = (const float*)d_in[0];
    const float* w_in   = (const float*)d_in[1];
    const float* g_in   = (const float*)d_in[2];
    const float* b_in   = (const float*)d_in[3];
    const float* w_out  = (const float*)d_in[4];
    const float* gout   = (const float*)d_in[5];
    const float* bout   = (const float*)d_in[6];
    const float* wqkv_h = (const float*)d_in[7];
    const float* rel_h  = (const float*)d_in[8];
    const float* ga_h   = (const float*)d_in[9];
    const float* ba_h   = (const float*)d_in[10];
    const float* go_h   = (const float*)d_in[11];
    const float* bo_h   = (const float*)d_in[12];
    const float* wqkv_w = (const float*)d_in[13];
    const float* rel_w  = (const float*)d_in[14];
    const float* ga_w   = (const float*)d_in[15];
    const float* ba_w   = (const float*)d_in[16];
    const float* go_w   = (const float*)d_in[17];
    const float* bo_w   = (const float*)d_in[18];
    float* out = (float*)d_out;

    float *conv1, *x1, *qkv, *outb, *x2, *x3, *co, *part, *sum, *sc, *sh, *scA, *shA, *Wt, *St;
    cudaGetSymbolAddress((void**)&conv1, g_conv1);
    cudaGetSymbolAddress((void**)&x1,    g_x1);
    cudaGetSymbolAddress((void**)&qkv,   g_qkv);
    cudaGetSymbolAddress((void**)&outb,  g_outb);
    cudaGetSymbolAddress((void**)&x2,    g_x2);
    cudaGetSymbolAddress((void**)&x3,    g_x3);
    cudaGetSymbolAddress((void**)&co,    g_co);
    cudaGetSymbolAddress((void**)&part,  g_part);
    cudaGetSymbolAddress((void**)&sum,   g_sum);
    cudaGetSymbolAddress((void**)&sc,    g_sc);
    cudaGetSymbolAddress((void**)&sh,    g_sh);
    cudaGetSymbolAddress((void**)&scA,   g_scA);
    cudaGetSymbolAddress((void**)&shA,   g_shA);
    cudaGetSymbolAddress((void**)&Wt,    g_Wt);
    cudaGetSymbolAddress((void**)&St,    g_St);

    const int SMEM_GEMM = 71680;
    cudaFuncSetAttribute(gemm_mma<256, 1>, cudaFuncAttributeMaxDynamicSharedMemorySize, SMEM_GEMM);
    cudaFuncSetAttribute(gemm_mma<128, 0>, cudaFuncAttributeMaxDynamicSharedMemorySize, SMEM_GEMM);
    cudaFuncSetAttribute(gemm_mma<128, 1>, cudaFuncAttributeMaxDynamicSharedMemorySize, SMEM_GEMM);

    const float invTok = 1.0f / 32768.0f;

    // conv_in: [128][32768] = w_in[128][256] * x_in
    gemm_mma<256, 1><<<dim3(256, 1), 256, SMEM_GEMM>>>(w_in, x_in, conv1);
    reduce_rows_k<<<128, 256>>>(conv1, 32768, sum);
    finalize_k<<<1, 256>>>(sum, g_in, b_in, 128, invTok, sc, sh);
    t1_k<<<dim3(128, 8), 256>>>(conv1, sc, sh, x1);

    // axial attention along H
    gemm_mma<128, 0><<<dim3(256, 2), 256, SMEM_GEMM>>>(wqkv_h, x1, qkv);
    rel_prep_k<<<1, 128>>>(rel_h, Wt, St);
    att_stats_k<<<512, 256>>>(qkv, Wt, St, part);
    attA_fin_k<<<24, 256>>>(part, ga_h, ba_h, scA, shA);
    att_main_k<<<4096, 256>>>(qkv, rel_h, scA, shA, outb);
    reduce_outb_k<<<256, 256>>>(outb, sum);
    finalize_k<<<1, 256>>>(sum, go_h, bo_h, 256, invTok, sc, sh);
    t2_k<<<dim3(128, 8), 256>>>(outb, sc, sh, x2);

    // axial attention along W
    gemm_mma<128, 0><<<dim3(256, 2), 256, SMEM_GEMM>>>(wqkv_w, x2, qkv);
    rel_prep_k<<<1, 128>>>(rel_w, Wt, St);
    att_stats_k<<<512, 256>>>(qkv, Wt, St, part);
    attA_fin_k<<<24, 256>>>(part, ga_w, ba_w, scA, shA);
    att_main_k<<<4096, 256>>>(qkv, rel_w, scA, shA, outb);
    reduce_outb_k<<<256, 256>>>(outb, sum);
    finalize_k<<<1, 256>>>(sum, go_w, bo_w, 256, invTok, sc, sh);
    t3_k<<<16384, 256>>>(outb, sc, sh, x3);

    // conv_out + BN + residual + relu
    gemm_mma<128, 1><<<dim3(256, 2), 256, SMEM_GEMM>>>(w_out, x3, co);
    reduce_rows_k<<<256, 256>>>(co, 32768, sum);
    finalize_k<<<1, 256>>>(sum, gout, bout, 256, invTok, sc, sh);
    final_k<<<32768, 256>>>(co, sc, sh, x_in, out);
}

// round 6
// speedup vs baseline: 1.4648x; 1.1131x over previous
#include <cuda_runtime.h>
#include <cuda_bf16.h>
#include <cstdint>

#define EPSV 1e-5f

// ------------------------- scratch (global, static) ------------------------
__device__ float g_conv1[128 * 32768];
__device__ float g_x1  [128 * 32768];
__device__ float g_qkv [256 * 32768];
__device__ float g_outb[2 * 512 * 128 * 64];
__device__ float g_x2  [128 * 32768];
__device__ float g_x3  [128 * 32768];
__device__ float g_co  [256 * 32768];
__device__ float g_part[512 * 24 * 2];
__device__ float g_sum [512];
__device__ float g_scA [24];
__device__ float g_shA [24];

// ========================= warp-MMA helpers (sm_80+) ========================
__device__ __forceinline__ uint32_t smem_u32(const void* p) {
    uint32_t a;
    asm("{ .reg .u64 t; cvta.to.shared.u64 t, %1; cvt.u32.u64 %0, t; }" : "=r"(a) : "l"(p));
    return a;
}
__device__ __forceinline__ void ldsm_x4(uint32_t (&r)[4], uint32_t addr) {
    asm volatile("ldmatrix.sync.aligned.m8n8.x4.shared.b16 {%0,%1,%2,%3}, [%4];"
                 : "=r"(r[0]), "=r"(r[1]), "=r"(r[2]), "=r"(r[3]) : "r"(addr));
}
__device__ __forceinline__ void ldsm_x4t(uint32_t (&r)[4], uint32_t addr) {
    asm volatile("ldmatrix.sync.aligned.m8n8.x4.trans.shared.b16 {%0,%1,%2,%3}, [%4];"
                 : "=r"(r[0]), "=r"(r[1]), "=r"(r[2]), "=r"(r[3]) : "r"(addr));
}
__device__ __forceinline__ void mma_bf16(float (&c)[4], const uint32_t (&a)[4],
                                         uint32_t b0, uint32_t b1) {
    asm volatile("mma.sync.aligned.m16n8k16.row.col.f32.bf16.bf16.f32 "
                 "{%0,%1,%2,%3}, {%4,%5,%6,%7}, {%8,%9}, {%0,%1,%2,%3};"
                 : "+f"(c[0]), "+f"(c[1]), "+f"(c[2]), "+f"(c[3])
                 : "r"(a[0]), "r"(a[1]), "r"(a[2]), "r"(a[3]), "r"(b0), "r"(b1));
}
__device__ __forceinline__ uint32_t pack_hilo(float x, float y, uint32_t& lo) {
    __nv_bfloat162 h = __floats2bfloat162_rn(x, y);
    float rx = x - __bfloat162float(h.x);
    float ry = y - __bfloat162float(h.y);
    __nv_bfloat162 l = __floats2bfloat162_rn(rx, ry);
    lo = *reinterpret_cast<uint32_t*>(&l);
    return *reinterpret_cast<uint32_t*>(&h);
}

// ======================= tensor-core GEMM (bf16 split, pipelined) ===========
// C[M][32768] = A[M][K] * B[K][32768], fp32 in/out.
// MODE 0: B row-major [K][32768].  MODE 1: B = [b][K][4096], n = b*4096+hw.
template <int KDIM, int MODE>
__global__ void __launch_bounds__(256) gemm_mma(const float* __restrict__ A,
                                                const float* __restrict__ Bm,
                                                float* __restrict__ C) {
    constexpr uint32_t AL_B = 128 * 72 * 2;        // 18432
    constexpr uint32_t BH_B = 2 * AL_B;            // 36864
    constexpr uint32_t BL_B = BH_B + 64 * 136 * 2; // 54272

    extern __shared__ __align__(16) char smem[];
    __nv_bfloat16* sAh = (__nv_bfloat16*)smem;
    __nv_bfloat16* sAl = (__nv_bfloat16*)(smem + AL_B);
    __nv_bfloat16* sBh = (__nv_bfloat16*)(smem + BH_B);
    __nv_bfloat16* sBl = (__nv_bfloat16*)(smem + BL_B);
    uint32_t sbase = smem_u32(smem);

    int tid = threadIdx.x, lane = tid & 31, wid = tid >> 5;
    int warp_m = wid & 3, warp_n = wid >> 2;
    int bn = blockIdx.x * 128;
    int bm = blockIdx.y * 128;

    int a_row_off = ((lane >> 3) & 1) * 8 + (lane & 7);
    int a_k_off   = (lane >> 4) * 8;
    int b_k_off   = a_row_off;
    int b_n_off   = a_k_off;

    float acc[2][8][4];
#pragma unroll
    for (int mt = 0; mt < 2; mt++)
#pragma unroll
        for (int nt = 0; nt < 8; nt++)
#pragma unroll
            for (int r = 0; r < 4; r++) acc[mt][nt][r] = 0.f;

    int aRow = tid >> 1, aQ = (tid & 1) * 32;
    int bRow = tid >> 2, bQ = (tid & 3) * 32;

    auto loadA = [&](int k0, float4 (&ra)[8]) {
        const float* ar = A + (size_t)(bm + aRow) * KDIM + k0 + aQ;
#pragma unroll
        for (int i = 0; i < 8; i++) ra[i] = *(const float4*)(ar + i * 4);
    };
    auto loadB = [&](int k0, float4 (&rb)[8]) {
        const float* br = (MODE == 0)
            ? Bm + (size_t)(k0 + bRow) * 32768 + bn + bQ
            : Bm + ((size_t)(bn >> 12) * KDIM + k0 + bRow) * 4096 + (bn & 4095) + bQ;
#pragma unroll
        for (int i = 0; i < 8; i++) rb[i] = *(const float4*)(br + i * 4);
    };

    float4 ra[8], rb[8];
    loadA(0, ra);
    loadB(0, rb);

    for (int k0 = 0; k0 < KDIM; k0 += 64) {
        // convert + store current chunk
        {
            uint32_t off = (uint32_t)(aRow * 72 + aQ);
#pragma unroll
            for (int i = 0; i < 8; i++) {
                uint32_t l0, l1;
                uint32_t h0 = pack_hilo(ra[i].x, ra[i].y, l0);
                uint32_t h1 = pack_hilo(ra[i].z, ra[i].w, l1);
                *(uint2*)(sAh + off + i * 4) = make_uint2(h0, h1);
                *(uint2*)(sAl + off + i * 4) = make_uint2(l0, l1);
            }
            off = (uint32_t)(bRow * 136 + bQ);
#pragma unroll
            for (int i = 0; i < 8; i++) {
                uint32_t l0, l1;
                uint32_t h0 = pack_hilo(rb[i].x, rb[i].y, l0);
                uint32_t h1 = pack_hilo(rb[i].z, rb[i].w, l1);
                *(uint2*)(sBh + off + i * 4) = make_uint2(h0, h1);
                *(uint2*)(sBl + off + i * 4) = make_uint2(l0, l1);
            }
        }
        __syncthreads();

        // prefetch next chunk (LDG latency hides under MMA below)
        if (k0 + 64 < KDIM) {
            loadA(k0 + 64, ra);
            loadB(k0 + 64, rb);
        }

#pragma unroll
        for (int ks = 0; ks < 4; ks++) {
            uint32_t ah[2][4], al[2][4], bh[4][4], bl[4][4];
#pragma unroll
            for (int mt = 0; mt < 2; mt++) {
                uint32_t addr = sbase +
                    (uint32_t)(((warp_m * 32 + mt * 16 + a_row_off) * 72 + ks * 16 + a_k_off) * 2);
                ldsm_x4(ah[mt], addr);
                ldsm_x4(al[mt], addr + AL_B);
            }
#pragma unroll
            for (int gi = 0; gi < 4; gi++) {
                uint32_t addr = sbase + BH_B +
                    (uint32_t)(((ks * 16 + b_k_off) * 136 + warp_n * 64 + gi * 16 + b_n_off) * 2);
                ldsm_x4t(bh[gi], addr);
                ldsm_x4t(bl[gi], addr + (BL_B - BH_B));
            }
#pragma unroll
            for (int mt = 0; mt < 2; mt++)
#pragma unroll
                for (int gi = 0; gi < 4; gi++)
#pragma unroll
                    for (int sub = 0; sub < 2; sub++) {
                        int nt = gi * 2 + sub;
                        mma_bf16(acc[mt][nt], ah[mt], bh[gi][2 * sub], bh[gi][2 * sub + 1]);
                        mma_bf16(acc[mt][nt], ah[mt], bl[gi][2 * sub], bl[gi][2 * sub + 1]);
                        mma_bf16(acc[mt][nt], al[mt], bh[gi][2 * sub], bh[gi][2 * sub + 1]);
                    }
        }
        __syncthreads();
    }

    int g = lane >> 2, t = lane & 3;
#pragma unroll
    for (int mt = 0; mt < 2; mt++) {
        int r0 = bm + warp_m * 32 + mt * 16 + g;
#pragma unroll
        for (int nt = 0; nt < 8; nt++) {
            int col = bn + warp_n * 64 + nt * 8 + 2 * t;
            *(float2*)(C + (size_t)r0 * 32768 + col) = make_float2(acc[mt][nt][0], acc[mt][nt][1]);
            *(float2*)(C + (size_t)(r0 + 8) * 32768 + col) = make_float2(acc[mt][nt][2], acc[mt][nt][3]);
        }
    }
}

// ------------------------------ helpers ------------------------------------
__device__ __forceinline__ float warpSum(float v) {
#pragma unroll
    for (int o = 16; o > 0; o >>= 1) v += __shfl_xor_sync(0xffffffffu, v, o);
    return v;
}
__device__ __forceinline__ void blockReduce2(float& a, float& b) {
    __shared__ float sa[8], sb2[8];
    int lane = threadIdx.x & 31, w = threadIdx.x >> 5;
#pragma unroll
    for (int o = 16; o > 0; o >>= 1) {
        a += __shfl_xor_sync(0xffffffffu, a, o);
        b += __shfl_xor_sync(0xffffffffu, b, o);
    }
    if (lane == 0) { sa[w] = a; sb2[w] = b; }
    __syncthreads();
    a = (threadIdx.x < 8) ? sa[threadIdx.x] : 0.f;
    b = (threadIdx.x < 8) ? sb2[threadIdx.x] : 0.f;
    if (w == 0) {
#pragma unroll
        for (int o = 4; o > 0; o >>= 1) {
            a += __shfl_xor_sync(0xffffffffu, a, o);
            b += __shfl_xor_sync(0xffffffffu, b, o);
        }
    }
}
// inline BN finalize: scale/shift for channel c from raw sums
__device__ __forceinline__ void bn_coef(const float* sums, const float* gamma,
                                        const float* beta, int c, float invN,
                                        float& s, float& t) {
    float mean = sums[c * 2] * invN;
    float var  = sums[c * 2 + 1] * invN - mean * mean;
    s = gamma[c] * rsqrtf(var + EPSV);
    t = beta[c] - mean * s;
}

// ---------------------- per-channel sum/sumsq -------------------------------
__global__ void __launch_bounds__(256) reduce_rows_k(const float* __restrict__ src,
                                                     int rowlen, float* __restrict__ out) {
    int ch = blockIdx.x;
    const float* p = src + (size_t)ch * rowlen;
    float s = 0.f, ss = 0.f;
    for (int i = threadIdx.x * 4; i < rowlen; i += 1024) {
        float4 v = *(const float4*)(p + i);
        s += v.x + v.y + v.z + v.w;
        ss = fmaf(v.x, v.x, ss); ss = fmaf(v.y, v.y, ss);
        ss = fmaf(v.z, v.z, ss); ss = fmaf(v.w, v.w, ss);
    }
    blockReduce2(s, ss);
    if (threadIdx.x == 0) { out[ch * 2] = s; out[ch * 2 + 1] = ss; }
}

__global__ void __launch_bounds__(256) reduce_outb_k(const float* __restrict__ outb,
                                                     float* __restrict__ out) {
    int ch = blockIdx.x;
    int s_ = ch >> 7, c2 = ch & 127;
    const float* base = outb + ((size_t)s_ * 512 * 128 + c2) * 64;
    float s = 0.f, ss = 0.f;
    for (int t = threadIdx.x * 4; t < 512 * 64; t += 1024) {
        int bb = t >> 6, d = t & 63;
        float4 v = *(const float4*)(base + bb * 8192 + d);
        s += v.x + v.y + v.z + v.w;
        ss = fmaf(v.x, v.x, ss); ss = fmaf(v.y, v.y, ss);
        ss = fmaf(v.z, v.z, ss); ss = fmaf(v.w, v.w, ss);
    }
    blockReduce2(s, ss);
    if (threadIdx.x == 0) { out[ch * 2] = s; out[ch * 2 + 1] = ss; }
}

// ----- T1: bn+relu + transpose -> x1[o][(b*64+w)*64 + h] (inline finalize) --
__global__ void __launch_bounds__(256) t1_k(const float* __restrict__ conv1,
                                            const float* __restrict__ sums,
                                            const float* __restrict__ gamma,
                                            const float* __restrict__ beta,
                                            float* __restrict__ x1) {
    __shared__ float tile[64][65];
    int o = blockIdx.x, b = blockIdx.y;
    float s, t;
    bn_coef(sums, gamma, beta, o, 1.0f / 32768.0f, s, t);
    const float* src = conv1 + (size_t)o * 32768 + b * 4096;
    float* dst = x1 + (size_t)o * 32768 + b * 4096;
#pragma unroll
    for (int it = 0; it < 4; it++) {
        int f = threadIdx.x + it * 256;
        int h = f >> 4, w4 = (f & 15) * 4;
        float4 v = *(const float4*)(src + h * 64 + w4);
        tile[w4 + 0][h] = fmaxf(fmaf(v.x, s, t), 0.f);
        tile[w4 + 1][h] = fmaxf(fmaf(v.y, s, t), 0.f);
        tile[w4 + 2][h] = fmaxf(fmaf(v.z, s, t), 0.f);
        tile[w4 + 3][h] = fmaxf(fmaf(v.w, s, t), 0.f);
    }
    __syncthreads();
#pragma unroll
    for (int it = 0; it < 4; it++) {
        int f = threadIdx.x + it * 256;
        int w = f >> 4, h4 = (f & 15) * 4;
        float4 v = make_float4(tile[w][h4], tile[w][h4 + 1], tile[w][h4 + 2], tile[w][h4 + 3]);
        *(float4*)(dst + w * 64 + h4) = v;
    }
}

// ----- closed-form attention BN stats (inline rel-table prep) ----------------
__global__ void __launch_bounds__(256) att_stats_k(const float* __restrict__ qkv,
                                                   const float* __restrict__ rel,
                                                   float* __restrict__ part) {
    __shared__ float Ws[72 * 64];
    __shared__ float Ss[16 * 64];
    int bb = blockIdx.x;
    int tid = threadIdx.x;
    // build windowed-correlation + window-sum tables from rel directly
    if (tid < 72) {
        int grp = (tid < 36) ? 0 : 1;
        int pr  = (tid < 36) ? tid : tid - 36;
        int i = 0, r = pr;
        while (r >= 8 - i) { r -= 8 - i; i++; }
        int i2 = i + r;
        const float* ra = rel + (grp * 8 + i)  * 127;
        const float* rb = rel + (grp * 8 + i2) * 127;
        float w = 0.f;
        for (int p = 0; p < 64; p++) w = fmaf(ra[p], rb[p], w);
        Ws[tid * 64 + 0] = w;
        for (int d = 1; d < 64; d++) {
            w += ra[d + 63] * rb[d + 63] - ra[d - 1] * rb[d - 1];
            Ws[tid * 64 + d] = w;
        }
    } else if (tid < 88) {
        int rr = tid - 72;
        const float* ra = rel + rr * 127;
        float s = 0.f;
        for (int p = 0; p < 64; p++) s += ra[p];
        Ss[rr * 64 + 0] = s;
        for (int d = 1; d < 64; d++) { s += ra[d + 63] - ra[d - 1]; Ss[rr * 64 + d] = s; }
    }
    __syncthreads();
    int h = tid >> 5, lane = tid & 31;
    float q[8][2], k[8][2];
#pragma unroll
    for (int i = 0; i < 8; i++) {
        const float* pq = qkv + (size_t)(i * 8 + h) * 32768 + bb * 64;
        const float* pk = qkv + (size_t)((8 + i) * 8 + h) * 32768 + bb * 64;
        q[i][0] = pq[lane]; q[i][1] = pq[lane + 32];
        k[i][0] = pk[lane]; k[i][1] = pk[lane + 32];
    }
    float s_qr = 0.f, s_kr = 0.f;
    float Qs[8], Ks[8];
#pragma unroll
    for (int i = 0; i < 8; i++) {
        s_qr = fmaf(q[i][0], Ss[i * 64 + lane], s_qr);
        s_qr = fmaf(q[i][1], Ss[i * 64 + lane + 32], s_qr);
        s_kr = fmaf(k[i][0], Ss[(8 + i) * 64 + lane], s_kr);
        s_kr = fmaf(k[i][1], Ss[(8 + i) * 64 + lane + 32], s_kr);
        Qs[i] = warpSum(q[i][0] + q[i][1]);
        Ks[i] = warpSum(k[i][0] + k[i][1]);
    }
    float s_dots = 0.f;
#pragma unroll
    for (int i = 0; i < 8; i++) s_dots = fmaf(Qs[i], Ks[i], s_dots);

    float ss_qr = 0.f, ss_kr = 0.f, ss_dots = 0.f;
    int pr = 0;
#pragma unroll
    for (int i = 0; i < 8; i++)
#pragma unroll
        for (int i2 = i; i2 < 8; i2++) {
            float coef = (i == i2) ? 1.f : 2.f;
            float pq0 = q[i][0] * q[i2][0], pq1 = q[i][1] * q[i2][1];
            float pk0 = k[i][0] * k[i2][0], pk1 = k[i][1] * k[i2][1];
            ss_qr += coef * (pq0 * Ws[pr * 64 + lane] + pq1 * Ws[pr * 64 + lane + 32]);
            ss_kr += coef * (pk0 * Ws[(36 + pr) * 64 + lane] + pk1 * Ws[(36 + pr) * 64 + lane + 32]);
            float gq = warpSum(pq0 + pq1);
            float gk = warpSum(pk0 + pk1);
            ss_dots = fmaf(coef * gq, gk, ss_dots);
            pr++;
        }
    s_qr = warpSum(s_qr); ss_qr = warpSum(ss_qr);
    s_kr = warpSum(s_kr); ss_kr = warpSum(ss_kr);
    if (lane == 0) {
        int base = bb * 24 + h * 3;
        part[(base + 0) * 2] = s_qr;   part[(base + 0) * 2 + 1] = ss_qr;
        part[(base + 1) * 2] = s_kr;   part[(base + 1) * 2 + 1] = ss_kr;
        part[(base + 2) * 2] = s_dots; part[(base + 2) * 2 + 1] = ss_dots;
    }
}

__global__ void __launch_bounds__(256) attA_fin_k(const float* __restrict__ part,
                                                  const float* __restrict__ ga,
                                                  const float* __restrict__ ba,
                                                  float* __restrict__ scA,
                                                  float* __restrict__ shA) {
    int ch = blockIdx.x;
    float s = 0.f, ss = 0.f;
    for (int bb = threadIdx.x; bb < 512; bb += 256) {
        s  += part[(bb * 24 + ch) * 2];
        ss += part[(bb * 24 + ch) * 2 + 1];
    }
    blockReduce2(s, ss);
    if (threadIdx.x == 0) {
        const float invN = 1.0f / 2097152.0f;
        float mean = s * invN;
        float var  = ss * invN - mean * mean;
        float sc = ga[ch] * rsqrtf(var + EPSV);
        scA[ch] = sc;
        shA[ch] = ba[ch] - mean * sc;
    }
}

// ----- attention mainloop (register softmax) ---------------------------------
__global__ void __launch_bounds__(256) att_main_k(const float* __restrict__ qkv,
                                                  const float* __restrict__ rel,
                                                  const float* __restrict__ scA,
                                                  const float* __restrict__ shA,
                                                  float* __restrict__ outb) {
    int bb = blockIdx.x >> 3, h = blockIdx.x & 7;
    __shared__ float qs[8][64], ks[8][64], vs[16][64];
    __shared__ float rqs[8][128], rks[8][128], rvs[16][128];
    __shared__ float attn[64][68];
    int tid = threadIdx.x;
    float sc0 = scA[h * 3 + 0], sh0 = shA[h * 3 + 0];
    float sc1 = scA[h * 3 + 1], sh1 = shA[h * 3 + 1];
    float sc2 = scA[h * 3 + 2], sh2 = shA[h * 3 + 2];

    for (int e = tid; e < 2048; e += 256) {
        int r = e >> 6, d = e & 63;
        float v = qkv[(r * 8 + h) * 32768 + bb * 64 + d];
        if (r < 8) qs[r][d] = v;
        else if (r < 16) ks[r - 8][d] = v;
        else vs[r - 16][d] = v;
    }
    for (int e = tid; e < 32 * 127; e += 256) {
        int r = e / 127, p = e % 127;
        float v = rel[e];
        if (r < 8) rqs[r][p] = v * sc0;
        else if (r < 16) rks[r - 8][p] = v * sc1;
        else rvs[r - 16][p] = v;
    }
    if (tid < 16) {
        rvs[tid][127] = 0.f;
        if (tid < 8) { rqs[tid][127] = 0.f; rks[tid][127] = 0.f; }
    }
    __syncthreads();

    // ---- logits (4d x 4j per thread) + register softmax ----
    {
        int d0 = (tid >> 4) << 2;
        int j0 = (tid & 15) << 2;
        int pb = d0 - j0 + 60;
        float shsum = sh0 + sh1 + sh2;
        float acc[4][4];
#pragma unroll
        for (int a = 0; a < 4; a++)
#pragma unroll
            for (int b = 0; b < 4; b++) acc[a][b] = shsum;
#pragma unroll
        for (int i = 0; i < 8; i++) {
            float4 qv = *(const float4*)&qs[i][d0];
            float4 kv = *(const float4*)&ks[i][d0];
            float4 kj = *(const float4*)&ks[i][j0];
            float r8q[8], r8k[8];
            *(float4*)&r8q[0] = *(const float4*)&rqs[i][pb];
            *(float4*)&r8q[4] = *(const float4*)&rqs[i][pb + 4];
            *(float4*)&r8k[0] = *(const float4*)&rks[i][pb];
            *(float4*)&r8k[4] = *(const float4*)&rks[i][pb + 4];
            float qa[4] = {qv.x, qv.y, qv.z, qv.w};
            float ka[4] = {kv.x, kv.y, kv.z, kv.w};
            float kja[4] = {kj.x, kj.y, kj.z, kj.w};
            float q2[4];
#pragma unroll
            for (int dd = 0; dd < 4; dd++) q2[dd] = qa[dd] * sc2;
#pragma unroll
            for (int dd = 0; dd < 4; dd++)
#pragma unroll
                for (int jj = 0; jj < 4; jj++) {
                    float t = acc[dd][jj];
                    t = fmaf(qa[dd], r8q[3 + dd - jj], t);
                    t = fmaf(ka[dd], r8k[3 + dd - jj], t);
                    t = fmaf(q2[dd], kja[jj], t);
                    acc[dd][jj] = t;
                }
        }
        // softmax rows d0..d0+3 over 16-lane j-groups (lane bits 0-3)
#pragma unroll
        for (int dd = 0; dd < 4; dd++) {
            float m = fmaxf(fmaxf(acc[dd][0], acc[dd][1]), fmaxf(acc[dd][2], acc[dd][3]));
#pragma unroll
            for (int o = 8; o > 0; o >>= 1) m = fmaxf(m, __shfl_xor_sync(0xffffffffu, m, o));
            float e0 = __expf(acc[dd][0] - m), e1 = __expf(acc[dd][1] - m);
            float e2 = __expf(acc[dd][2] - m), e3 = __expf(acc[dd][3] - m);
            float s = e0 + e1 + e2 + e3;
#pragma unroll
            for (int o = 8; o > 0; o >>= 1) s += __shfl_xor_sync(0xffffffffu, s, o);
            float inv = 1.f / s;
            *(float4*)&attn[d0 + dd][j0] = make_float4(e0 * inv, e1 * inv, e2 * inv, e3 * inv);
        }
    }
    __syncthreads();

    // ---- sv & sve ----
    {
        int dg = tid >> 4;
        int ig = (tid >> 2) & 3;
        int jq = tid & 3;
        int d0 = dg << 2, i0 = ig << 2;
        float asv[4][4], asve[4][4];
#pragma unroll
        for (int a = 0; a < 4; a++)
#pragma unroll
            for (int b = 0; b < 4; b++) { asv[a][b] = 0.f; asve[a][b] = 0.f; }

        for (int j4 = jq * 16; j4 < jq * 16 + 16; j4 += 4) {
            float a[4][4];
#pragma unroll
            for (int dd = 0; dd < 4; dd++)
                *(float4*)a[dd] = *(const float4*)&attn[d0 + dd][j4];
            int pb = d0 - j4 + 60;
#pragma unroll
            for (int ii = 0; ii < 4; ii++) {
                int i = i0 + ii;
                float vv[4];
                *(float4*)vv = *(const float4*)&vs[i][j4];
                float r8[8];
                *(float4*)&r8[0] = *(const float4*)&rvs[i][pb];
                *(float4*)&r8[4] = *(const float4*)&rvs[i][pb + 4];
#pragma unroll
                for (int dd = 0; dd < 4; dd++)
#pragma unroll
                    for (int jj = 0; jj < 4; jj++) {
                        asv[ii][dd]  = fmaf(a[dd][jj], vv[jj], asv[ii][dd]);
                        asve[ii][dd] = fmaf(a[dd][jj], r8[3 + dd - jj], asve[ii][dd]);
                    }
            }
        }
#pragma unroll
        for (int ii = 0; ii < 4; ii++)
#pragma unroll
            for (int dd = 0; dd < 4; dd++) {
                asv[ii][dd]  += __shfl_xor_sync(0xffffffffu, asv[ii][dd], 1);
                asv[ii][dd]  += __shfl_xor_sync(0xffffffffu, asv[ii][dd], 2);
                asve[ii][dd] += __shfl_xor_sync(0xffffffffu, asve[ii][dd], 1);
                asve[ii][dd] += __shfl_xor_sync(0xffffffffu, asve[ii][dd], 2);
            }
        if (jq == 0) {
#pragma unroll
            for (int ii = 0; ii < 4; ii++) {
                int c2 = h * 16 + i0 + ii;
                size_t o0 = ((size_t)bb * 128 + c2) * 64 + d0;
                *(float4*)&outb[o0] = make_float4(asve[ii][0], asve[ii][1], asve[ii][2], asve[ii][3]);
                *(float4*)&outb[o0 + (size_t)512 * 128 * 64] =
                    make_float4(asv[ii][0], asv[ii][1], asv[ii][2], asv[ii][3]);
            }
        }
    }
}

// ----- T2: BN + sum over s + transpose -> x2[c2][(b*64+h)*64+w] --------------
__global__ void __launch_bounds__(256) t2_k(const float* __restrict__ outb,
                                            const float* __restrict__ sums,
                                            const float* __restrict__ gamma,
                                            const float* __restrict__ beta,
                                            float* __restrict__ x2) {
    __shared__ float tile[64][65];
    int c2 = blockIdx.x, b = blockIdx.y;
    float s0, h0, s1, h1;
    bn_coef(sums, gamma, beta, c2,       1.0f / 32768.0f, s0, h0);
    bn_coef(sums, gamma, beta, 128 + c2, 1.0f / 32768.0f, s1, h1);
    const float* base0 = outb + ((size_t)(b * 64) * 128 + c2) * 64;
    const float* base1 = base0 + (size_t)512 * 128 * 64;
#pragma unroll
    for (int it = 0; it < 4; it++) {
        int f = threadIdx.x + it * 256;
        int w = f >> 4, h4 = (f & 15) * 4;
        float4 v0 = *(const float4*)(base0 + w * 8192 + h4);
        float4 v1 = *(const float4*)(base1 + w * 8192 + h4);
        tile[h4 + 0][w] = fmaf(v0.x, s0, h0) + fmaf(v1.x, s1, h1);
        tile[h4 + 1][w] = fmaf(v0.y, s0, h0) + fmaf(v1.y, s1, h1);
        tile[h4 + 2][w] = fmaf(v0.z, s0, h0) + fmaf(v1.z, s1, h1);
        tile[h4 + 3][w] = fmaf(v0.w, s0, h0) + fmaf(v1.w, s1, h1);
    }
    __syncthreads();
    float* dst = x2 + (size_t)c2 * 32768 + b * 4096;
#pragma unroll
    for (int it = 0; it < 4; it++) {
        int f = threadIdx.x + it * 256;
        int h = f >> 4, w4 = (f & 15) * 4;
        float4 v = make_float4(tile[h][w4], tile[h][w4 + 1], tile[h][w4 + 2], tile[h][w4 + 3]);
        *(float4*)(dst + h * 64 + w4) = v;
    }
}

// ----- T3: BN + sum over s + relu -> x3[b][c2][h][w] -------------------------
__global__ void __launch_bounds__(256) t3_k(const float* __restrict__ outb,
                                            const float* __restrict__ sums,
                                            const float* __restrict__ gamma,
                                            const float* __restrict__ beta,
                                            float* __restrict__ x3) {
    int g = (blockIdx.x * 256 + threadIdx.x) * 4;
    int w  = g & 63;
    int r  = g >> 6;
    int h  = r & 63;
    int c2 = (r >> 6) & 127;
    int b  = r >> 13;
    int bb = b * 64 + h;
    float s0, h0, s1, h1;
    bn_coef(sums, gamma, beta, c2,       1.0f / 32768.0f, s0, h0);
    bn_coef(sums, gamma, beta, 128 + c2, 1.0f / 32768.0f, s1, h1);
    float4 v0 = *(const float4*)(outb + ((size_t)bb * 128 + c2) * 64 + w);
    float4 v1 = *(const float4*)(outb + ((size_t)(512 + bb) * 128 + c2) * 64 + w);
    float4 o;
    o.x = fmaxf(fmaf(v0.x, s0, h0) + fmaf(v1.x, s1, h1), 0.f);
    o.y = fmaxf(fmaf(v0.y, s0, h0) + fmaf(v1.y, s1, h1), 0.f);
    o.z = fmaxf(fmaf(v0.z, s0, h0) + fmaf(v1.z, s1, h1), 0.f);
    o.w = fmaxf(fmaf(v0.w, s0, h0) + fmaf(v1.w, s1, h1), 0.f);
    *(float4*)(x3 + g) = o;
}

// ----- final: y = relu(bn(conv_out) + x_in) ----------------------------------
__global__ void __launch_bounds__(256) final_k(const float* __restrict__ co,
                                               const float* __restrict__ sums,
                                               const float* __restrict__ gamma,
                                               const float* __restrict__ beta,
                                               const float* __restrict__ x_in,
                                               float* __restrict__ out) {
    int g = (blockIdx.x * 256 + threadIdx.x) * 4;
    int o  = (g >> 12) & 255;
    int b  = g >> 20;
    int hw = g & 4095;
    float s, t;
    bn_coef(sums, gamma, beta, o, 1.0f / 32768.0f, s, t);
    float4 c = *(const float4*)(co + (size_t)o * 32768 + b * 4096 + hw);
    float4 x = *(const float4*)(x_in + g);
    float4 y;
    y.x = fmaxf(fmaf(c.x, s, t) + x.x, 0.f);
    y.y = fmaxf(fmaf(c.y, s, t) + x.y, 0.f);
    y.z = fmaxf(fmaf(c.z, s, t) + x.z, 0.f);
    y.w = fmaxf(fmaf(c.w, s, t) + x.w, 0.f);
    *(float4*)(out + g) = y;
}

// ---------------------------------------------------------------------------
extern "C" void kernel_launch(void* const* d_in, const int* in_sizes, int n_in,
                              void* d_out, int out_size) {
    const float* x_in   = (const float*)d_in[0];
    const float* w_in   = (const float*)d_in[1];
    const float* g_in   = (const float*)d_in[2];
    const float* b_in   = (const float*)d_in[3];
    const float* w_out  = (const float*)d_in[4];
    const float* gout   = (const float*)d_in[5];
    const float* bout   = (const float*)d_in[6];
    const float* wqkv_h = (const float*)d_in[7];
    const float* rel_h  = (const float*)d_in[8];
    const float* ga_h   = (const float*)d_in[9];
    const float* ba_h   = (const float*)d_in[10];
    const float* go_h   = (const float*)d_in[11];
    const float* bo_h   = (const float*)d_in[12];
    const float* wqkv_w = (const float*)d_in[13];
    const float* rel_w  = (const float*)d_in[14];
    const float* ga_w   = (const float*)d_in[15];
    const float* ba_w   = (const float*)d_in[16];
    const float* go_w   = (const float*)d_in[17];
    const float* bo_w   = (const float*)d_in[18];
    float* out = (float*)d_out;

    float *conv1, *x1, *qkv, *outb, *x2, *x3, *co, *part, *sum, *scA, *shA;
    cudaGetSymbolAddress((void**)&conv1, g_conv1);
    cudaGetSymbolAddress((void**)&x1,    g_x1);
    cudaGetSymbolAddress((void**)&qkv,   g_qkv);
    cudaGetSymbolAddress((void**)&outb,  g_outb);
    cudaGetSymbolAddress((void**)&x2,    g_x2);
    cudaGetSymbolAddress((void**)&x3,    g_x3);
    cudaGetSymbolAddress((void**)&co,    g_co);
    cudaGetSymbolAddress((void**)&part,  g_part);
    cudaGetSymbolAddress((void**)&sum,   g_sum);
    cudaGetSymbolAddress((void**)&scA,   g_scA);
    cudaGetSymbolAddress((void**)&shA,   g_shA);

    const int SMEM_GEMM = 71680;
    cudaFuncSetAttribute(gemm_mma<256, 1>, cudaFuncAttributeMaxDynamicSharedMemorySize, SMEM_GEMM);
    cudaFuncSetAttribute(gemm_mma<128, 0>, cudaFuncAttributeMaxDynamicSharedMemorySize, SMEM_GEMM);
    cudaFuncSetAttribute(gemm_mma<128, 1>, cudaFuncAttributeMaxDynamicSharedMemorySize, SMEM_GEMM);

    // conv_in: [128][32768] = w_in[128][256] * x_in
    gemm_mma<256, 1><<<dim3(256, 1), 256, SMEM_GEMM>>>(w_in, x_in, conv1);
    reduce_rows_k<<<128, 256>>>(conv1, 32768, sum);
    t1_k<<<dim3(128, 8), 256>>>(conv1, sum, g_in, b_in, x1);

    // axial attention along H
    gemm_mma<128, 0><<<dim3(256, 2), 256, SMEM_GEMM>>>(wqkv_h, x1, qkv);
    att_stats_k<<<512, 256>>>(qkv, rel_h, part);
    attA_fin_k<<<24, 256>>>(part, ga_h, ba_h, scA, shA);
    att_main_k<<<4096, 256>>>(qkv, rel_h, scA, shA, outb);
    reduce_outb_k<<<256, 256>>>(outb, sum);
    t2_k<<<dim3(128, 8), 256>>>(outb, sum, go_h, bo_h, x2);

    // axial attention along W
    gemm_mma<128, 0><<<dim3(256, 2), 256, SMEM_GEMM>>>(wqkv_w, x2, qkv);
    att_stats_k<<<512, 256>>>(qkv, rel_w, part);
    attA_fin_k<<<24, 256>>>(part, ga_w, ba_w, scA, shA);
    att_main_k<<<4096, 256>>>(qkv, rel_w, scA, shA, outb);
    reduce_outb_k<<<256, 256>>>(outb, sum);
    t3_k<<<4096, 256>>>(outb, sum, go_w, bo_w, x3);

    // conv_out + BN + residual + relu
    gemm_mma<128, 1><<<dim3(256, 2), 256, SMEM_GEMM>>>(w_out, x3, co);
    reduce_rows_k<<<256, 256>>>(co, 32768, sum);
    final_k<<<8192, 256>>>(co, sum, gout, bout, x_in, out);
}